// round 9
// baseline (speedup 1.0000x reference)
#include <cuda_runtime.h>
#include <cuda_fp16.h>
#include <cstdint>

// ======================= constants =======================
#define D_FEAT  64
#define KNN     5
#define KH      192            // 3 x 64 fp16 (hi/lo cross-term expansion)
#define TPB     256
#define NB      79             // number of 128-row blocks
#define NPAIR   (NB * (NB + 1) / 2)   // 3160 upper-triangular block pairs
#define NSLOT   NB
#define NPADR   (NB * 128)     // 10112
#define NEG_INF (-3.402823466e38f)
#define PAD_SQ  1.0e30f        // padded-row squared norm -> d ~ -1e30, never selected

// smem layout (bytes): row stride 400 (200 halfs) -> ldmatrix conflict-free
#define SAB      400
#define SM_A     0            // 128 x 400 = 51200
#define SM_B     51200        // 128 x 400 = 51200
#define SM_SQA   102400       // 128 floats
#define SM_SQB   102912       // 128 floats
#define SMEM_DYN 103424
// epilogue overlays (A/B tile region reused after the MMA):
#define TSTRIDE  133          // words; bank = (5*cl + rl) % 32 -> conflict-free scans
#define SM_T     0            // 128 cols x 133 x 4 = 68096
#define SM_PRV   68096        // row partial lists: 128*5 floats
#define SM_PRI   70656        // 128*5 ints
#define SM_PCV   73216        // col partial lists: 128*5 floats
#define SM_PCI   75776        // 128*5 ints  (end 78336 < 102400)

// ======================= device scratch (static; no allocs) =======================
__device__ __half g_xa[(size_t)NPADR * KH];   // [hi, lo, hi]
__device__ __half g_xb[(size_t)NPADR * KH];   // [hi, hi, lo]
__device__ float  g_sq[NPADR];
__device__ float  g_topv[(size_t)NPADR * NSLOT * KNN];
__device__ int    g_topi[(size_t)NPADR * NSLOT * KNN];

// ======================= baseline-ISA PTX helpers (NO tcgen05) =======================
__device__ __forceinline__ uint32_t smem_to_u32(const void* p) {
    uint32_t a;
    asm("{ .reg .u64 t; cvta.to.shared.u64 t, %1; cvt.u32.u64 %0, t; }" : "=r"(a) : "l"(p));
    return a;
}
__device__ __forceinline__ void cp16(uint32_t dst, const void* src) {
    asm volatile("cp.async.cg.shared.global [%0], [%1], 16;" :: "r"(dst), "l"(src));
}
#define CP_COMMIT() asm volatile("cp.async.commit_group;" ::: "memory")
#define CP_WAIT(n)  asm volatile("cp.async.wait_group %0;" :: "n"(n) : "memory")

__device__ __forceinline__ void ldsm_x4(uint32_t* r, uint32_t addr) {
    asm volatile("ldmatrix.sync.aligned.m8n8.x4.shared.b16 {%0,%1,%2,%3}, [%4];"
                 : "=r"(r[0]), "=r"(r[1]), "=r"(r[2]), "=r"(r[3]) : "r"(addr));
}
__device__ __forceinline__ void mma16816(float* c, const uint32_t* a, const uint32_t* b) {
    asm volatile("mma.sync.aligned.m16n8k16.row.col.f32.f16.f16.f32 "
                 "{%0,%1,%2,%3}, {%4,%5,%6,%7}, {%8,%9}, {%0,%1,%2,%3};"
                 : "+f"(c[0]), "+f"(c[1]), "+f"(c[2]), "+f"(c[3])
                 : "r"(a[0]), "r"(a[1]), "r"(a[2]), "r"(a[3]), "r"(b[0]), "r"(b[1]));
}

// ======================= top-k =======================
__device__ __forceinline__ bool knn_better(float v, int i, float v2, int i2) {
    return (v > v2) || (v == v2 && i < i2);
}
__device__ __forceinline__ void topk_insert5(float* tv, int* ti, float v, int i) {
    bool cont = true;
#pragma unroll
    for (int s = 0; s < KNN; ++s) {
        bool up = (s < KNN - 1) && knn_better(v, i, tv[s + 1], ti[s + 1]);
        if (cont) {
            if (up) { tv[s] = tv[s + 1]; ti[s] = ti[s + 1]; }
            else    { tv[s] = v;          ti[s] = i; cont = false; }
        }
    }
}

// ======================= prep: element-parallel fp16 split + warp-reduced norms ======
__global__ void prep_kernel(const float* __restrict__ x, int N) {
    const int idx = blockIdx.x * blockDim.x + threadIdx.x;
    if (idx >= NPADR * 16) return;
    const int i  = idx >> 4;
    const int kq = idx & 15;
    const int k  = kq * 4;

    float4 v4 = make_float4(0.f, 0.f, 0.f, 0.f);
    if (i < N) v4 = *(const float4*)(x + (size_t)i * D_FEAT + k);

    __half h[4], l[4];
    const float vv[4] = {v4.x, v4.y, v4.z, v4.w};
    float psum = 0.f;
#pragma unroll
    for (int e = 0; e < 4; ++e) {
        psum += vv[e] * vv[e];
        h[e] = __float2half_rn(vv[e]);
        l[e] = __float2half_rn(vv[e] - __half2float(h[e]));
    }
    uint2 hp, lp;
    hp.x = __half_as_ushort(h[0]) | ((uint32_t)__half_as_ushort(h[1]) << 16);
    hp.y = __half_as_ushort(h[2]) | ((uint32_t)__half_as_ushort(h[3]) << 16);
    lp.x = __half_as_ushort(l[0]) | ((uint32_t)__half_as_ushort(l[1]) << 16);
    lp.y = __half_as_ushort(l[2]) | ((uint32_t)__half_as_ushort(l[3]) << 16);

    __half* a = g_xa + (size_t)i * KH;
    __half* b = g_xb + (size_t)i * KH;
    *(uint2*)(a + k)       = hp;   // A: [hi, lo, hi]
    *(uint2*)(a + 64 + k)  = lp;
    *(uint2*)(a + 128 + k) = hp;
    *(uint2*)(b + k)       = hp;   // B: [hi, hi, lo]
    *(uint2*)(b + 64 + k)  = hp;
    *(uint2*)(b + 128 + k) = lp;

#pragma unroll
    for (int s = 8; s > 0; s >>= 1) psum += __shfl_xor_sync(0xffffffffu, psum, s);
    // padded rows get a huge norm -> their distances are ~ -1e30 and never win;
    // this removes all gc<N / gi<N compares from the hot scans.
    if (kq == 0) g_sq[i] = (i < N) ? psum : PAD_SQ;
}

// ======================= one 128x128 block-pair per CTA (J >= I) =======================
__global__ __launch_bounds__(TPB, 2)
void gemm_knn_kernel(float* __restrict__ out, int N) {
    extern __shared__ __align__(16) char smem[];
    const uint32_t sb = smem_to_u32(smem);
    float* sqA = (float*)(smem + SM_SQA);
    float* sqB = (float*)(smem + SM_SQB);

    const int tid  = threadIdx.x;
    const int w    = tid >> 5;
    const int lane = tid & 31;
    const int wm   = w & 3;       // 4 M-warps (32 rows each)
    const int wn   = w >> 2;      // 2 N-warps (64 cols each)
    const int g    = lane >> 2;
    const int q    = lane & 3;

    // pair index -> upper-triangular (I, J)  (uniform short loop, ~negligible)
    const int pg = blockIdx.x;
    int p = pg, I = 0, rem = NB;
    while (p >= rem) { p -= rem; --rem; ++I; }
    const int J = I + p;
    const int row0 = I * 128;
    const int col0 = J * 128;

    // ---- ldmatrix per-thread base offsets ----
    const uint32_t aAddr0 = sb + SM_A + (uint32_t)(wm * 32 + (lane & 15)) * SAB + ((lane >> 4) * 8) * 2;
    const uint32_t aAddr1 = aAddr0 + 16 * SAB;
    uint32_t bAddr[4];
#pragma unroll
    for (int nb2 = 0; nb2 < 4; ++nb2)
        bAddr[nb2] = sb + SM_B + (uint32_t)(wn * 64 + nb2 * 16 + ((lane >> 4) << 3) + (lane & 7)) * SAB
                     + (((lane >> 3) & 1) * 8) * 2;

    // ---- async loads: A rows (block I from g_xa), B rows (block J from g_xb) ----
    for (int idx = tid; idx < 128 * 24; idx += TPB) {
        int r = idx / 24, c = idx - r * 24;
        cp16(sb + SM_A + (uint32_t)r * SAB + c * 16,
             (const char*)(g_xa + (size_t)(row0 + r) * KH) + c * 16);
    }
    for (int idx = tid; idx < 128 * 24; idx += TPB) {
        int r = idx / 24, c = idx - r * 24;
        cp16(sb + SM_B + (uint32_t)r * SAB + c * 16,
             (const char*)(g_xb + (size_t)(col0 + r) * KH) + c * 16);
    }
    if (tid < 128) sqA[tid] = g_sq[row0 + tid];
    else           sqB[tid - 128] = g_sq[col0 + tid - 128];
    CP_COMMIT();

    // ---- zero this CTA's slice of the output while cp.async loads are in flight ----
    {
        const unsigned Z   = (unsigned)N * (unsigned)N;          // 1e8 fits u32
        const unsigned per = (((Z + NPAIR - 1u) / NPAIR) + 3u) & ~3u;
        const unsigned lo  = (unsigned)pg * per;
        unsigned hi = lo + per; if (hi > Z) hi = Z;
        if (hi > lo) {
            float4* o4 = (float4*)(out + lo);
            const unsigned n4 = (hi - lo) >> 2;
            const float4 zz = make_float4(0.f, 0.f, 0.f, 0.f);
            for (unsigned i4 = tid; i4 < n4; i4 += TPB) __stcs(o4 + i4, zz);
            const unsigned tail = lo + (n4 << 2);
            if ((unsigned)tid < (hi - tail)) __stcs(out + tail + tid, 0.f);
        }
    }

    CP_WAIT(0);
    __syncthreads();

    // ---- 128x128x192 tile: 12 k-steps, warp tile 32x64 (16 HMMA / 6 LDSM) ----
    float c[2][8][4];
#pragma unroll
    for (int mb = 0; mb < 2; ++mb)
#pragma unroll
        for (int nb = 0; nb < 8; ++nb)
#pragma unroll
            for (int e = 0; e < 4; ++e) c[mb][nb][e] = 0.f;

#pragma unroll
    for (int ks = 0; ks < 12; ++ks) {
        uint32_t a0[4], a1[4], b[4][4];
        ldsm_x4(a0, aAddr0 + ks * 32);
        ldsm_x4(a1, aAddr1 + ks * 32);
#pragma unroll
        for (int nb2 = 0; nb2 < 4; ++nb2) ldsm_x4(b[nb2], bAddr[nb2] + ks * 32);
#pragma unroll
        for (int nb2 = 0; nb2 < 4; ++nb2) {
            mma16816(c[0][nb2 * 2],     a0, &b[nb2][0]);
            mma16816(c[0][nb2 * 2 + 1], a0, &b[nb2][2]);
            mma16816(c[1][nb2 * 2],     a1, &b[nb2][0]);
            mma16816(c[1][nb2 * 2 + 1], a1, &b[nb2][2]);
        }
    }

    __syncthreads();   // all ldsm reads done; A/B region can be overlaid by T

    // ---- store distances ONCE into T (d is symmetric; both scans reuse it) ----
    float* T = (float*)(smem + SM_T);
    {
        float sa0[4];
#pragma unroll
        for (int mb = 0; mb < 2; ++mb)
#pragma unroll
            for (int rr = 0; rr < 2; ++rr)
                sa0[mb * 2 + rr] = sqA[wm * 32 + mb * 16 + rr * 8 + g];
#pragma unroll
        for (int nb = 0; nb < 8; ++nb) {
            const int clb = wn * 64 + nb * 8 + q * 2;
            const float sb0 = sqB[clb];
            const float sb1 = sqB[clb + 1];
#pragma unroll
            for (int mb = 0; mb < 2; ++mb)
#pragma unroll
                for (int rr = 0; rr < 2; ++rr) {
                    const int li = mb * 2 + rr;
                    const int rl = wm * 32 + mb * 16 + rr * 8 + g;
                    const float d0 = (2.f * c[mb][nb][rr * 2]     - sa0[li]) - sb0;
                    const float d1 = (2.f * c[mb][nb][rr * 2 + 1] - sa0[li]) - sb1;
                    T[clb * TSTRIDE + rl]       = d0;
                    T[(clb + 1) * TSTRIDE + rl] = d1;
                }
        }
    }
    __syncthreads();

    // ---- scans: 2 threads per row / per column, no bounds checks (padding trick) ----
    const int lidx = tid & 127;
    const int half = tid >> 7;

    float rv[KNN]; int ri[KNN];
#pragma unroll
    for (int m = 0; m < KNN; ++m) { rv[m] = NEG_INF; ri[m] = 0x7fffffff; }
    {
        const float* Trow = T + half * 64 * TSTRIDE + lidx;
#pragma unroll 4
        for (int i2 = 0; i2 < 64; ++i2) {
            const float d = Trow[i2 * TSTRIDE];
            const int gc = col0 + half * 64 + i2;
            if (knn_better(d, gc, rv[0], ri[0])) topk_insert5(rv, ri, d, gc);
        }
    }
    float cv[KNN]; int ci[KNN];
#pragma unroll
    for (int m = 0; m < KNN; ++m) { cv[m] = NEG_INF; ci[m] = 0x7fffffff; }
    if (J > I) {
        const float* Tcol = T + lidx * TSTRIDE + half * 64;
#pragma unroll 4
        for (int i2 = 0; i2 < 64; ++i2) {
            const float d = Tcol[i2];
            const int gi = row0 + half * 64 + i2;
            if (knn_better(d, gi, cv[0], ci[0])) topk_insert5(cv, ci, d, gi);
        }
    }

    // ---- half-exchange + final per-(row/col) lists -> global slots ----
    float* prv = (float*)(smem + SM_PRV); int* pri = (int*)(smem + SM_PRI);
    float* pcv = (float*)(smem + SM_PCV); int* pci = (int*)(smem + SM_PCI);
    if (half) {
#pragma unroll
        for (int m = 0; m < KNN; ++m) { prv[lidx * KNN + m] = rv[m]; pri[lidx * KNN + m] = ri[m]; }
        if (J > I) {
#pragma unroll
            for (int m = 0; m < KNN; ++m) { pcv[lidx * KNN + m] = cv[m]; pci[lidx * KNN + m] = ci[m]; }
        }
    }
    __syncthreads();
    if (!half) {
#pragma unroll
        for (int m = 0; m < KNN; ++m) {
            const float v = prv[lidx * KNN + m];
            const int   j = pri[lidx * KNN + m];
            if (knn_better(v, j, rv[0], ri[0])) topk_insert5(rv, ri, v, j);
        }
        const size_t baseR = ((size_t)(row0 + lidx) * NSLOT + J) * KNN;
#pragma unroll
        for (int m = 0; m < KNN; ++m) { g_topv[baseR + m] = rv[m]; g_topi[baseR + m] = ri[m]; }

        if (J > I) {
#pragma unroll
            for (int m = 0; m < KNN; ++m) {
                const float v = pcv[lidx * KNN + m];
                const int   j = pci[lidx * KNN + m];
                if (knn_better(v, j, cv[0], ci[0])) topk_insert5(cv, ci, v, j);
            }
            const size_t baseC = ((size_t)(col0 + lidx) * NSLOT + I) * KNN;
#pragma unroll
            for (int m = 0; m < KNN; ++m) { g_topv[baseC + m] = cv[m]; g_topi[baseC + m] = ci[m]; }
        }
    }
}

// ======================= parallel merge (warp per row) + symmetric scatter ============
__global__ void merge_scatter_kernel(float* __restrict__ out, int N) {
    const int wid  = threadIdx.x >> 5;
    const int lane = threadIdx.x & 31;
    const int row  = blockIdx.x * 8 + wid;
    if (row >= N) return;

    float mv[KNN]; int mi[KNN];
#pragma unroll
    for (int m = 0; m < KNN; ++m) { mv[m] = NEG_INF; mi[m] = 0x7fffffff; }

    // lane-local scan over slots lane, lane+32, lane+64 (coalesced 20B chunks)
    const size_t base0 = (size_t)row * NSLOT * KNN;
    for (int s = lane; s < NSLOT; s += 32) {
#pragma unroll
        for (int m = 0; m < KNN; ++m) {
            float v = g_topv[base0 + s * KNN + m];
            int   j = g_topi[base0 + s * KNN + m];
            if (j < N && knn_better(v, j, mv[0], mi[0])) topk_insert5(mv, mi, v, j);
        }
    }
    // warp tree-merge of sorted top-5 lists (each candidate j occurs in exactly one slot)
#pragma unroll
    for (int off = 16; off > 0; off >>= 1) {
        float ov[KNN]; int oi[KNN];
#pragma unroll
        for (int m = 0; m < KNN; ++m) {
            ov[m] = __shfl_down_sync(0xffffffffu, mv[m], off);
            oi[m] = __shfl_down_sync(0xffffffffu, mi[m], off);
        }
        if (lane < off) {
#pragma unroll
            for (int m = 0; m < KNN; ++m)
                if (oi[m] < N && knn_better(ov[m], oi[m], mv[0], mi[0]))
                    topk_insert5(mv, mi, ov[m], oi[m]);
        }
    }
    // self (d~0) is always the row max; reference zeroes the diagonal -> skip j == row.
    if (lane == 0) {
#pragma unroll
        for (int m = 0; m < KNN; ++m) {
            const int j = mi[m]; const float v = mv[m];
            if (j < N && j != row) {
                atomicAdd(out + (size_t)row * N + j, v);
                atomicAdd(out + (size_t)j * N + row, v);
            }
        }
    }
}

// ======================= launch =======================
extern "C" void kernel_launch(void* const* d_in, const int* in_sizes, int n_in,
                              void* d_out, int out_size) {
    const float* x = (const float*)d_in[0];
    const int N = in_sizes[0] / D_FEAT;   // 10000 here (<= NPADR)
    float* out = (float*)d_out;

    cudaFuncSetAttribute(gemm_knn_kernel, cudaFuncAttributeMaxDynamicSharedMemorySize, SMEM_DYN);

    prep_kernel<<<(NPADR * 16 + 255) / 256, 256>>>(x, N);
    gemm_knn_kernel<<<NPAIR, TPB, SMEM_DYN>>>(out, N);
    merge_scatter_kernel<<<(N + 7) / 8, 256>>>(out, N);
}

// round 10
// speedup vs baseline: 1.2864x; 1.2864x over previous
#include <cuda_runtime.h>
#include <cuda_fp16.h>
#include <cstdint>

// ======================= constants =======================
#define D_FEAT  64
#define KNN     5
#define KH      192            // 3 x 64 fp16 (hi/lo cross-term expansion)
#define TPB     256
#define NB      79             // number of 128-row blocks
#define NPAIR   (NB * (NB + 1) / 2)   // 3160 upper-triangular block pairs
#define NSLOT   NB
#define NPADR   (NB * 128)     // 10112
#define NEG_INF (-3.402823466e38f)

// smem layout (bytes): row stride 400 (200 halfs) -> ldmatrix conflict-free
#define SAB      400
#define SM_A     0            // 128 x 400 = 51200
#define SM_B     51200        // 128 x 400 = 51200
#define SM_SQA   102400       // 128 floats
#define SM_SQB   102912       // 128 floats
#define SMEM_DYN 103424
// overlays (A/B regions reused after the MMA):
#define SM_MV    0                    // 128*8*5 floats = 20480
#define SM_MI    20480                // 128*8*5 ints
#define TSTRIDE  133                  // words; conflict-free column scans
#define SM_CLV   69632                // 128*5 floats (col-side half-lists)
#define SM_CLI   72192                // 128*5 ints

// ======================= device scratch (static; no allocs) =======================
__device__ __half g_xa[(size_t)NPADR * KH];   // [hi, lo, hi]
__device__ __half g_xb[(size_t)NPADR * KH];   // [hi, hi, lo]
__device__ float  g_sq[NPADR];
__device__ float  g_topv[(size_t)NPADR * NSLOT * KNN];
__device__ int    g_topi[(size_t)NPADR * NSLOT * KNN];

// ======================= baseline-ISA PTX helpers (NO tcgen05) =======================
__device__ __forceinline__ uint32_t smem_to_u32(const void* p) {
    uint32_t a;
    asm("{ .reg .u64 t; cvta.to.shared.u64 t, %1; cvt.u32.u64 %0, t; }" : "=r"(a) : "l"(p));
    return a;
}
__device__ __forceinline__ void cp16(uint32_t dst, const void* src) {
    asm volatile("cp.async.cg.shared.global [%0], [%1], 16;" :: "r"(dst), "l"(src));
}
#define CP_COMMIT() asm volatile("cp.async.commit_group;" ::: "memory")
#define CP_WAIT(n)  asm volatile("cp.async.wait_group %0;" :: "n"(n) : "memory")

__device__ __forceinline__ void ldsm_x4(uint32_t* r, uint32_t addr) {
    asm volatile("ldmatrix.sync.aligned.m8n8.x4.shared.b16 {%0,%1,%2,%3}, [%4];"
                 : "=r"(r[0]), "=r"(r[1]), "=r"(r[2]), "=r"(r[3]) : "r"(addr));
}
__device__ __forceinline__ void mma16816(float* c, const uint32_t* a, const uint32_t* b) {
    asm volatile("mma.sync.aligned.m16n8k16.row.col.f32.f16.f16.f32 "
                 "{%0,%1,%2,%3}, {%4,%5,%6,%7}, {%8,%9}, {%0,%1,%2,%3};"
                 : "+f"(c[0]), "+f"(c[1]), "+f"(c[2]), "+f"(c[3])
                 : "r"(a[0]), "r"(a[1]), "r"(a[2]), "r"(a[3]), "r"(b[0]), "r"(b[1]));
}

// ======================= top-k =======================
__device__ __forceinline__ bool knn_better(float v, int i, float v2, int i2) {
    return (v > v2) || (v == v2 && i < i2);
}
__device__ __forceinline__ void topk_insert5(float* tv, int* ti, float v, int i) {
    bool cont = true;
#pragma unroll
    for (int s = 0; s < KNN; ++s) {
        bool up = (s < KNN - 1) && knn_better(v, i, tv[s + 1], ti[s + 1]);
        if (cont) {
            if (up) { tv[s] = tv[s + 1]; ti[s] = ti[s + 1]; }
            else    { tv[s] = v;          ti[s] = i; cont = false; }
        }
    }
}

// ======================= prep: element-parallel fp16 split + warp-reduced norms ======
__global__ void prep_kernel(const float* __restrict__ x, int N) {
    const int idx = blockIdx.x * blockDim.x + threadIdx.x;
    if (idx >= NPADR * 16) return;
    const int i  = idx >> 4;
    const int kq = idx & 15;
    const int k  = kq * 4;

    float4 v4 = make_float4(0.f, 0.f, 0.f, 0.f);
    if (i < N) v4 = *(const float4*)(x + (size_t)i * D_FEAT + k);

    __half h[4], l[4];
    const float vv[4] = {v4.x, v4.y, v4.z, v4.w};
    float psum = 0.f;
#pragma unroll
    for (int e = 0; e < 4; ++e) {
        psum += vv[e] * vv[e];
        h[e] = __float2half_rn(vv[e]);
        l[e] = __float2half_rn(vv[e] - __half2float(h[e]));
    }
    uint2 hp, lp;
    hp.x = __half_as_ushort(h[0]) | ((uint32_t)__half_as_ushort(h[1]) << 16);
    hp.y = __half_as_ushort(h[2]) | ((uint32_t)__half_as_ushort(h[3]) << 16);
    lp.x = __half_as_ushort(l[0]) | ((uint32_t)__half_as_ushort(l[1]) << 16);
    lp.y = __half_as_ushort(l[2]) | ((uint32_t)__half_as_ushort(l[3]) << 16);

    __half* a = g_xa + (size_t)i * KH;
    __half* b = g_xb + (size_t)i * KH;
    *(uint2*)(a + k)       = hp;   // A: [hi, lo, hi]
    *(uint2*)(a + 64 + k)  = lp;
    *(uint2*)(a + 128 + k) = hp;
    *(uint2*)(b + k)       = hp;   // B: [hi, hi, lo]
    *(uint2*)(b + 64 + k)  = hp;
    *(uint2*)(b + 128 + k) = lp;

#pragma unroll
    for (int s = 8; s > 0; s >>= 1) psum += __shfl_xor_sync(0xffffffffu, psum, s);
    if (kq == 0) g_sq[i] = psum;
}

// ======================= one 128x128 block-pair per CTA (J >= I) — R6-proven =========
__global__ __launch_bounds__(TPB, 2)
void gemm_knn_kernel(float* __restrict__ out, int N) {
    extern __shared__ __align__(16) char smem[];
    const uint32_t sb = smem_to_u32(smem);
    float* sqA = (float*)(smem + SM_SQA);
    float* sqB = (float*)(smem + SM_SQB);

    const int tid  = threadIdx.x;
    const int w    = tid >> 5;
    const int lane = tid & 31;
    const int wm   = w & 3;       // 4 M-warps (32 rows each)
    const int wn   = w >> 2;      // 2 N-warps (64 cols each)
    const int g    = lane >> 2;
    const int q    = lane & 3;

    // blockIdx.x -> upper-triangular pair (I, J)
    int p = blockIdx.x, I = 0, rem = NB;
    while (p >= rem) { p -= rem; --rem; ++I; }
    const int J = I + p;
    const int row0 = I * 128;
    const int col0 = J * 128;

    // ---- ldmatrix per-thread base offsets ----
    const uint32_t aAddr0 = sb + SM_A + (uint32_t)(wm * 32 + (lane & 15)) * SAB + ((lane >> 4) * 8) * 2;
    const uint32_t aAddr1 = aAddr0 + 16 * SAB;
    uint32_t bAddr[4];
#pragma unroll
    for (int nb2 = 0; nb2 < 4; ++nb2)
        bAddr[nb2] = sb + SM_B + (uint32_t)(wn * 64 + nb2 * 16 + ((lane >> 4) << 3) + (lane & 7)) * SAB
                     + (((lane >> 3) & 1) * 8) * 2;

    // ---- async loads: A rows (block I from g_xa), B rows (block J from g_xb) ----
    for (int idx = tid; idx < 128 * 24; idx += TPB) {
        int r = idx / 24, c = idx - r * 24;
        cp16(sb + SM_A + (uint32_t)r * SAB + c * 16,
             (const char*)(g_xa + (size_t)(row0 + r) * KH) + c * 16);
    }
    for (int idx = tid; idx < 128 * 24; idx += TPB) {
        int r = idx / 24, c = idx - r * 24;
        cp16(sb + SM_B + (uint32_t)r * SAB + c * 16,
             (const char*)(g_xb + (size_t)(col0 + r) * KH) + c * 16);
    }
    if (tid < 128) sqA[tid] = g_sq[row0 + tid];
    else           sqB[tid - 128] = g_sq[col0 + tid - 128];
    CP_COMMIT();

    // ---- zero this CTA's slice of the output while cp.async loads are in flight ----
    {
        const unsigned Z   = (unsigned)N * (unsigned)N;
        const unsigned per = (((Z + NPAIR - 1u) / NPAIR) + 3u) & ~3u;
        const unsigned lo  = (unsigned)blockIdx.x * per;
        unsigned hi = lo + per; if (hi > Z) hi = Z;
        if (hi > lo) {
            float4* o4 = (float4*)(out + lo);
            const unsigned n4 = (hi - lo) >> 2;
            const float4 zz = make_float4(0.f, 0.f, 0.f, 0.f);
            for (unsigned i4 = tid; i4 < n4; i4 += TPB) __stcs(o4 + i4, zz);
            const unsigned tail = lo + (n4 << 2);
            if ((unsigned)tid < (hi - tail)) __stcs(out + tail + tid, 0.f);
        }
    }

    CP_WAIT(0);
    __syncthreads();

    // ---- 128x128x192 tile: 12 k-steps, warp tile 32x64 (16 HMMA / 6 LDSM) ----
    float c[2][8][4];
#pragma unroll
    for (int mb = 0; mb < 2; ++mb)
#pragma unroll
        for (int nb = 0; nb < 8; ++nb)
#pragma unroll
            for (int e = 0; e < 4; ++e) c[mb][nb][e] = 0.f;

#pragma unroll
    for (int ks = 0; ks < 12; ++ks) {
        uint32_t a0[4], a1[4], b[4][4];
        ldsm_x4(a0, aAddr0 + ks * 32);
        ldsm_x4(a1, aAddr1 + ks * 32);
#pragma unroll
        for (int nb2 = 0; nb2 < 4; ++nb2) ldsm_x4(b[nb2], bAddr[nb2] + ks * 32);
#pragma unroll
        for (int nb2 = 0; nb2 < 4; ++nb2) {
            mma16816(c[0][nb2 * 2],     a0, &b[nb2][0]);
            mma16816(c[0][nb2 * 2 + 1], a0, &b[nb2][2]);
            mma16816(c[1][nb2 * 2],     a1, &b[nb2][0]);
            mma16816(c[1][nb2 * 2 + 1], a1, &b[nb2][2]);
        }
    }

    // ---- row-side epilogue: per-thread top-5 over 64 REGISTER values ----
    float tv[4][KNN]; int ti[4][KNN]; float sa0[4];
#pragma unroll
    for (int mb = 0; mb < 2; ++mb)
#pragma unroll
        for (int rr = 0; rr < 2; ++rr) {
            const int li = mb * 2 + rr;
            sa0[li] = sqA[wm * 32 + mb * 16 + rr * 8 + g];
#pragma unroll
            for (int m = 0; m < KNN; ++m) { tv[li][m] = NEG_INF; ti[li][m] = 0x7fffffff; }
        }
#pragma unroll
    for (int nb = 0; nb < 8; ++nb)
#pragma unroll
        for (int e0 = 0; e0 < 2; ++e0) {
            const int cl = wn * 64 + nb * 8 + q * 2 + e0;
            const float sb_ = sqB[cl];
            const int gc = col0 + cl;
#pragma unroll
            for (int mb = 0; mb < 2; ++mb)
#pragma unroll
                for (int rr = 0; rr < 2; ++rr) {
                    const int li = mb * 2 + rr;
                    const float d = (2.f * c[mb][nb][rr * 2 + e0] - sa0[li]) - sb_;
                    if (gc < N && knn_better(d, gc, tv[li][0], ti[li][0]))
                        topk_insert5(tv[li], ti[li], d, gc);
                }
        }

    // ---- in-CTA row merge: 8 contributor lists per row -> slot J ----
    __syncthreads();   // all ldmatrix reads done; safe to overlay A region
    float* mvs = (float*)(smem + SM_MV);
    int*   mis = (int*)(smem + SM_MI);
#pragma unroll
    for (int mb = 0; mb < 2; ++mb)
#pragma unroll
        for (int rr = 0; rr < 2; ++rr) {
            const int li   = mb * 2 + rr;
            const int rloc = wm * 32 + mb * 16 + rr * 8 + g;
            const int slot = wn * 4 + q;
            const int base = (rloc * 8 + slot) * KNN;
#pragma unroll
            for (int m = 0; m < KNN; ++m) { mvs[base + m] = tv[li][m]; mis[base + m] = ti[li][m]; }
        }
    __syncthreads();
    if (tid < 128) {
        float mv[KNN]; int mi[KNN];
#pragma unroll
        for (int m = 0; m < KNN; ++m) { mv[m] = NEG_INF; mi[m] = 0x7fffffff; }
        for (int s = 0; s < 8; ++s) {
#pragma unroll
            for (int m = 0; m < KNN; ++m) {
                float v = mvs[(tid * 8 + s) * KNN + m];
                int   j = mis[(tid * 8 + s) * KNN + m];
                if (j < N && knn_better(v, j, mv[0], mi[0])) topk_insert5(mv, mi, v, j);
            }
        }
        const size_t base = ((size_t)(row0 + tid) * NSLOT + J) * KNN;
#pragma unroll
        for (int m = 0; m < KNN; ++m) { g_topv[base + m] = mv[m]; g_topi[base + m] = mi[m]; }
    }

    // ---- col-side (off-diagonal tiles only): transpose via smem, harvest slot I ----
    if (J > I) {
        __syncthreads();   // row-merge readers done; overlay T over mvs/mis
        float* T = (float*)smem;
#pragma unroll
        for (int mb = 0; mb < 2; ++mb)
#pragma unroll
            for (int nb = 0; nb < 8; ++nb)
#pragma unroll
                for (int rr = 0; rr < 2; ++rr)
#pragma unroll
                    for (int e0 = 0; e0 < 2; ++e0) {
                        const int cl = wn * 64 + nb * 8 + q * 2 + e0;
                        const int rl = wm * 32 + mb * 16 + rr * 8 + g;
                        T[cl * TSTRIDE + rl] = c[mb][nb][rr * 2 + e0];
                    }
        __syncthreads();

        const int col  = tid & 127;
        const int half = tid >> 7;
        const float sbj = sqB[col];
        float mv[KNN]; int mi[KNN];
#pragma unroll
        for (int m = 0; m < KNN; ++m) { mv[m] = NEG_INF; mi[m] = 0x7fffffff; }
#pragma unroll 4
        for (int i2 = 0; i2 < 64; ++i2) {
            const int rl = half * 64 + i2;
            const float f = T[col * TSTRIDE + rl];
            const float d = (2.f * f - sbj) - sqA[rl];
            const int gi = row0 + rl;
            if (gi < N && knn_better(d, gi, mv[0], mi[0])) topk_insert5(mv, mi, d, gi);
        }
        float* clv = (float*)(smem + SM_CLV);
        int*   cli = (int*)(smem + SM_CLI);
        if (half) {
#pragma unroll
            for (int m = 0; m < KNN; ++m) { clv[col * KNN + m] = mv[m]; cli[col * KNN + m] = mi[m]; }
        }
        __syncthreads();
        if (!half) {
#pragma unroll
            for (int m = 0; m < KNN; ++m) {
                float v = clv[col * KNN + m];
                int   j = cli[col * KNN + m];
                if (j < N && knn_better(v, j, mv[0], mi[0])) topk_insert5(mv, mi, v, j);
            }
            const size_t base = ((size_t)(col0 + col) * NSLOT + I) * KNN;
#pragma unroll
            for (int m = 0; m < KNN; ++m) { g_topv[base + m] = mv[m]; g_topi[base + m] = mi[m]; }
        }
    }
}

// ======================= parallel merge (warp per row) + symmetric scatter ============
__global__ void merge_scatter_kernel(float* __restrict__ out, int N) {
    const int wid  = threadIdx.x >> 5;
    const int lane = threadIdx.x & 31;
    const int row  = blockIdx.x * 8 + wid;
    if (row >= N) return;

    float mv[KNN]; int mi[KNN];
#pragma unroll
    for (int m = 0; m < KNN; ++m) { mv[m] = NEG_INF; mi[m] = 0x7fffffff; }

    // lane-local scan over slots lane, lane+32, lane+64 (coalesced 20B chunks)
    const size_t base0 = (size_t)row * NSLOT * KNN;
    for (int s = lane; s < NSLOT; s += 32) {
#pragma unroll
        for (int m = 0; m < KNN; ++m) {
            float v = g_topv[base0 + s * KNN + m];
            int   j = g_topi[base0 + s * KNN + m];
            if (j < N && knn_better(v, j, mv[0], mi[0])) topk_insert5(mv, mi, v, j);
        }
    }
    // warp tree-merge of sorted top-5 lists (each candidate j occurs in exactly one slot)
#pragma unroll
    for (int off = 16; off > 0; off >>= 1) {
        float ov[KNN]; int oi[KNN];
#pragma unroll
        for (int m = 0; m < KNN; ++m) {
            ov[m] = __shfl_down_sync(0xffffffffu, mv[m], off);
            oi[m] = __shfl_down_sync(0xffffffffu, mi[m], off);
        }
        if (lane < off) {
#pragma unroll
            for (int m = 0; m < KNN; ++m)
                if (oi[m] < N && knn_better(ov[m], oi[m], mv[0], mi[0]))
                    topk_insert5(mv, mi, ov[m], oi[m]);
        }
    }
    // self (d~0) is always the row max; reference zeroes the diagonal -> skip j == row.
    if (lane == 0) {
#pragma unroll
        for (int m = 0; m < KNN; ++m) {
            const int j = mi[m]; const float v = mv[m];
            if (j < N && j != row) {
                atomicAdd(out + (size_t)row * N + j, v);
                atomicAdd(out + (size_t)j * N + row, v);
            }
        }
    }
}

// ======================= launch =======================
extern "C" void kernel_launch(void* const* d_in, const int* in_sizes, int n_in,
                              void* d_out, int out_size) {
    const float* x = (const float*)d_in[0];
    const int N = in_sizes[0] / D_FEAT;   // 10000 here (<= NPADR)
    float* out = (float*)d_out;

    cudaFuncSetAttribute(gemm_knn_kernel, cudaFuncAttributeMaxDynamicSharedMemorySize, SMEM_DYN);

    prep_kernel<<<(NPADR * 16 + 255) / 256, 256>>>(x, N);
    gemm_knn_kernel<<<NPAIR, TPB, SMEM_DYN>>>(out, N);
    merge_scatter_kernel<<<(N + 7) / 8, 256>>>(out, N);
}

// round 11
// speedup vs baseline: 1.4729x; 1.1449x over previous
#include <cuda_runtime.h>
#include <cuda_fp16.h>
#include <cstdint>

// ======================= constants =======================
#define D_FEAT  64
#define KNN     5
#define KH      192            // 3 x 64 fp16 (hi/lo cross-term expansion)
#define TPB     256
#define NB      79             // number of 128-row blocks
#define NPAIR   (NB * (NB + 1) / 2)   // 3160 upper-triangular block pairs
#define NSLOT   NB
#define NPADR   (NB * 128)     // 10112
#define NEG_INF (-3.402823466e38f)
#define PAD_SQ  1.0e30f        // padded-row norm -> d ~ -1e30, never selected

// smem layout (bytes): row stride 400 (200 halfs) -> ldmatrix conflict-free
#define SAB      400
#define SM_A     0            // 128 x 400 = 51200
#define SM_B     51200        // 128 x 400 = 51200
#define SM_SQA   102400       // 128 floats
#define SM_SQB   102912       // 128 floats
#define SMEM_DYN 103424
// epilogue overlays (A/B tile region reused after the MMA):
#define TSTRIDE  132          // words; 132*4=528B rows; 16B-aligned, conflict-free
#define SM_T     0            // 128 cols x 132 x 4 = 67584
#define SM_RMV   67584        // row partial lists: 2(wn) x 128 x 5 floats = 5120
#define SM_RMI   72704        // same, ints
#define SM_CLV   77824        // col half-lists: 128 x 5 floats = 2560
#define SM_CLI   80384        // 128 x 5 ints   (end 82944 < 102400)

// ======================= device scratch (static; no allocs) =======================
__device__ __half g_xa[(size_t)NPADR * KH];   // [hi, lo, hi]
__device__ __half g_xb[(size_t)NPADR * KH];   // [hi, hi, lo]
__device__ float  g_sq[NPADR];
__device__ float  g_topv[(size_t)NPADR * NSLOT * KNN];
__device__ int    g_topi[(size_t)NPADR * NSLOT * KNN];

// ======================= baseline-ISA PTX helpers (NO tcgen05) =======================
__device__ __forceinline__ uint32_t smem_to_u32(const void* p) {
    uint32_t a;
    asm("{ .reg .u64 t; cvta.to.shared.u64 t, %1; cvt.u32.u64 %0, t; }" : "=r"(a) : "l"(p));
    return a;
}
__device__ __forceinline__ void cp16(uint32_t dst, const void* src) {
    asm volatile("cp.async.cg.shared.global [%0], [%1], 16;" :: "r"(dst), "l"(src));
}
#define CP_COMMIT() asm volatile("cp.async.commit_group;" ::: "memory")
#define CP_WAIT(n)  asm volatile("cp.async.wait_group %0;" :: "n"(n) : "memory")

__device__ __forceinline__ void ldsm_x4(uint32_t* r, uint32_t addr) {
    asm volatile("ldmatrix.sync.aligned.m8n8.x4.shared.b16 {%0,%1,%2,%3}, [%4];"
                 : "=r"(r[0]), "=r"(r[1]), "=r"(r[2]), "=r"(r[3]) : "r"(addr));
}
__device__ __forceinline__ void mma16816(float* c, const uint32_t* a, const uint32_t* b) {
    asm volatile("mma.sync.aligned.m16n8k16.row.col.f32.f16.f16.f32 "
                 "{%0,%1,%2,%3}, {%4,%5,%6,%7}, {%8,%9}, {%0,%1,%2,%3};"
                 : "+f"(c[0]), "+f"(c[1]), "+f"(c[2]), "+f"(c[3])
                 : "r"(a[0]), "r"(a[1]), "r"(a[2]), "r"(a[3]), "r"(b[0]), "r"(b[1]));
}

// ======================= top-k =======================
__device__ __forceinline__ bool knn_better(float v, int i, float v2, int i2) {
    return (v > v2) || (v == v2 && i < i2);
}
// Full insert (tie-aware) for merges of lists with interleaved index ranges.
__device__ __forceinline__ void topk_insert5(float* tv, int* ti, float v, int i) {
    bool cont = true;
#pragma unroll
    for (int s = 0; s < KNN; ++s) {
        bool up = (s < KNN - 1) && knn_better(v, i, tv[s + 1], ti[s + 1]);
        if (cont) {
            if (up) { tv[s] = tv[s + 1]; ti[s] = ti[s + 1]; }
            else    { tv[s] = v;          ti[s] = i; cont = false; }
        }
    }
}
// Strict insert: valid when candidate indices are strictly increasing within the
// scan (on an exact value tie the stored lower-index entry must stay above).
__device__ __forceinline__ void topk_insert5_gt(float* tv, int* ti, float v, int i) {
    bool cont = true;
#pragma unroll
    for (int s = 0; s < KNN; ++s) {
        bool up = (s < KNN - 1) && (v > tv[s + 1]);
        if (cont) {
            if (up) { tv[s] = tv[s + 1]; ti[s] = ti[s + 1]; }
            else    { tv[s] = v;          ti[s] = i; cont = false; }
        }
    }
}

// ======================= prep: element-parallel fp16 split + warp-reduced norms ======
__global__ void prep_kernel(const float* __restrict__ x, int N) {
    const int idx = blockIdx.x * blockDim.x + threadIdx.x;
    if (idx >= NPADR * 16) return;
    const int i  = idx >> 4;
    const int kq = idx & 15;
    const int k  = kq * 4;

    float4 v4 = make_float4(0.f, 0.f, 0.f, 0.f);
    if (i < N) v4 = *(const float4*)(x + (size_t)i * D_FEAT + k);

    __half h[4], l[4];
    const float vv[4] = {v4.x, v4.y, v4.z, v4.w};
    float psum = 0.f;
#pragma unroll
    for (int e = 0; e < 4; ++e) {
        psum += vv[e] * vv[e];
        h[e] = __float2half_rn(vv[e]);
        l[e] = __float2half_rn(vv[e] - __half2float(h[e]));
    }
    uint2 hp, lp;
    hp.x = __half_as_ushort(h[0]) | ((uint32_t)__half_as_ushort(h[1]) << 16);
    hp.y = __half_as_ushort(h[2]) | ((uint32_t)__half_as_ushort(h[3]) << 16);
    lp.x = __half_as_ushort(l[0]) | ((uint32_t)__half_as_ushort(l[1]) << 16);
    lp.y = __half_as_ushort(l[2]) | ((uint32_t)__half_as_ushort(l[3]) << 16);

    __half* a = g_xa + (size_t)i * KH;
    __half* b = g_xb + (size_t)i * KH;
    *(uint2*)(a + k)       = hp;   // A: [hi, lo, hi]
    *(uint2*)(a + 64 + k)  = lp;
    *(uint2*)(a + 128 + k) = hp;
    *(uint2*)(b + k)       = hp;   // B: [hi, hi, lo]
    *(uint2*)(b + 64 + k)  = hp;
    *(uint2*)(b + 128 + k) = lp;

#pragma unroll
    for (int s = 8; s > 0; s >>= 1) psum += __shfl_xor_sync(0xffffffffu, psum, s);
    if (kq == 0) g_sq[i] = (i < N) ? psum : PAD_SQ;
}

// ======================= one 128x128 block-pair per CTA (J >= I) =======================
__global__ __launch_bounds__(TPB, 2)
void gemm_knn_kernel(float* __restrict__ out, int N) {
    extern __shared__ __align__(16) char smem[];
    const uint32_t sb = smem_to_u32(smem);
    float* sqA = (float*)(smem + SM_SQA);
    float* sqB = (float*)(smem + SM_SQB);

    const int tid  = threadIdx.x;
    const int w    = tid >> 5;
    const int lane = tid & 31;
    const int wm   = w & 3;       // 4 M-warps (32 rows each)
    const int wn   = w >> 2;      // 2 N-warps (64 cols each)
    const int g    = lane >> 2;
    const int q    = lane & 3;

    // blockIdx.x -> upper-triangular pair (I, J), closed form + fixup
    const int pg = blockIdx.x;
    int I;
    {
        const float s0 = 2.f * NB + 1.f;                    // 159
        I = (int)((s0 - sqrtf(s0 * s0 - 8.f * (float)pg)) * 0.5f);
        if (I < 0) I = 0; if (I > NB - 1) I = NB - 1;
        // tri(i) = i*NB - i*(i-1)/2
        while (I > 0 && (I * NB - ((I * (I - 1)) >> 1)) > pg) --I;
        while (I < NB - 1 && ((I + 1) * NB - (((I + 1) * I) >> 1)) <= pg) ++I;
    }
    const int J = I + (pg - (I * NB - ((I * (I - 1)) >> 1)));
    const int row0 = I * 128;
    const int col0 = J * 128;

    // ---- ldmatrix per-thread base offsets ----
    const uint32_t aAddr0 = sb + SM_A + (uint32_t)(wm * 32 + (lane & 15)) * SAB + ((lane >> 4) * 8) * 2;
    const uint32_t aAddr1 = aAddr0 + 16 * SAB;
    uint32_t bAddr[4];
#pragma unroll
    for (int nb2 = 0; nb2 < 4; ++nb2)
        bAddr[nb2] = sb + SM_B + (uint32_t)(wn * 64 + nb2 * 16 + ((lane >> 4) << 3) + (lane & 7)) * SAB
                     + (((lane >> 3) & 1) * 8) * 2;

    // ---- async loads: A rows (block I from g_xa), B rows (block J from g_xb) ----
    for (int idx = tid; idx < 128 * 24; idx += TPB) {
        int r = idx / 24, c = idx - r * 24;
        cp16(sb + SM_A + (uint32_t)r * SAB + c * 16,
             (const char*)(g_xa + (size_t)(row0 + r) * KH) + c * 16);
    }
    for (int idx = tid; idx < 128 * 24; idx += TPB) {
        int r = idx / 24, c = idx - r * 24;
        cp16(sb + SM_B + (uint32_t)r * SAB + c * 16,
             (const char*)(g_xb + (size_t)(col0 + r) * KH) + c * 16);
    }
    if (tid < 128) sqA[tid] = g_sq[row0 + tid];
    else           sqB[tid - 128] = g_sq[col0 + tid - 128];
    CP_COMMIT();

    // ---- zero this CTA's slice of the output while cp.async loads are in flight ----
    {
        const unsigned Z   = (unsigned)N * (unsigned)N;
        const unsigned per = (((Z + NPAIR - 1u) / NPAIR) + 3u) & ~3u;
        const unsigned lo  = (unsigned)pg * per;
        unsigned hi = lo + per; if (hi > Z) hi = Z;
        if (hi > lo) {
            float4* o4 = (float4*)(out + lo);
            const unsigned n4 = (hi - lo) >> 2;
            const float4 zz = make_float4(0.f, 0.f, 0.f, 0.f);
#pragma unroll 4
            for (unsigned i4 = tid; i4 < n4; i4 += TPB) __stcs(o4 + i4, zz);
            const unsigned tail = lo + (n4 << 2);
            if ((unsigned)tid < (hi - tail)) __stcs(out + tail + tid, 0.f);
        }
    }

    CP_WAIT(0);
    __syncthreads();

    // ---- 128x128x192 tile: 12 k-steps, warp tile 32x64 (16 HMMA / 6 LDSM) ----
    float c[2][8][4];
#pragma unroll
    for (int mb = 0; mb < 2; ++mb)
#pragma unroll
        for (int nb = 0; nb < 8; ++nb)
#pragma unroll
            for (int e = 0; e < 4; ++e) c[mb][nb][e] = 0.f;

#pragma unroll
    for (int ks = 0; ks < 12; ++ks) {
        uint32_t a0[4], a1[4], b[4][4];
        ldsm_x4(a0, aAddr0 + ks * 32);
        ldsm_x4(a1, aAddr1 + ks * 32);
#pragma unroll
        for (int nb2 = 0; nb2 < 4; ++nb2) ldsm_x4(b[nb2], bAddr[nb2] + ks * 32);
#pragma unroll
        for (int nb2 = 0; nb2 < 4; ++nb2) {
            mma16816(c[0][nb2 * 2],     a0, &b[nb2][0]);
            mma16816(c[0][nb2 * 2 + 1], a0, &b[nb2][2]);
            mma16816(c[1][nb2 * 2],     a1, &b[nb2][0]);
            mma16816(c[1][nb2 * 2 + 1], a1, &b[nb2][2]);
        }
    }

    __syncthreads();   // all ldmatrix reads done -> A/B region reusable as T

    // ---- store RAW dot to T (col side recomputes d with its own rounding) ----
    float* T = (float*)(smem + SM_T);
    if (J > I) {
#pragma unroll
        for (int mb = 0; mb < 2; ++mb)
#pragma unroll
            for (int nb = 0; nb < 8; ++nb)
#pragma unroll
                for (int rr = 0; rr < 2; ++rr)
#pragma unroll
                    for (int e0 = 0; e0 < 2; ++e0) {
                        const int cl = wn * 64 + nb * 8 + q * 2 + e0;
                        const int rl = wm * 32 + mb * 16 + rr * 8 + g;
                        T[cl * TSTRIDE + rl] = c[mb][nb][rr * 2 + e0];
                    }
    }

    // ---- transform c in place: d = (2*dot - sa) - sb  (exact reference order) ----
    float sa0[4];
#pragma unroll
    for (int mb = 0; mb < 2; ++mb)
#pragma unroll
        for (int rr = 0; rr < 2; ++rr)
            sa0[mb * 2 + rr] = sqA[wm * 32 + mb * 16 + rr * 8 + g];
#pragma unroll
    for (int nb = 0; nb < 8; ++nb)
#pragma unroll
        for (int e0 = 0; e0 < 2; ++e0) {
            const float sb_ = sqB[wn * 64 + nb * 8 + q * 2 + e0];
#pragma unroll
            for (int mb = 0; mb < 2; ++mb)
#pragma unroll
                for (int rr = 0; rr < 2; ++rr)
                    c[mb][nb][rr * 2 + e0] =
                        fmaf(c[mb][nb][rr * 2 + e0], 2.f, -sa0[mb * 2 + rr]) - sb_;
        }

    // ---- row-side scan: 4 ILP lists over register values (strict >, no bounds) ----
    float tv[4][KNN]; int ti[4][KNN];
#pragma unroll
    for (int li = 0; li < 4; ++li)
#pragma unroll
        for (int m = 0; m < KNN; ++m) { tv[li][m] = NEG_INF; ti[li][m] = 0x7fffffff; }
#pragma unroll
    for (int nb = 0; nb < 8; ++nb)
#pragma unroll
        for (int e0 = 0; e0 < 2; ++e0) {
            const int gc = col0 + wn * 64 + nb * 8 + q * 2 + e0;
#pragma unroll
            for (int mb = 0; mb < 2; ++mb)
#pragma unroll
                for (int rr = 0; rr < 2; ++rr) {
                    const int li = mb * 2 + rr;
                    const float d = c[mb][nb][rr * 2 + e0];
                    if (d > tv[li][0]) topk_insert5_gt(tv[li], ti[li], d, gc);
                }
        }

    // ---- q-lane shuffle merge (divergence-free): 8 lists/row -> 2 lists/row ----
#pragma unroll
    for (int off = 1; off <= 2; off <<= 1) {
#pragma unroll
        for (int li = 0; li < 4; ++li) {
            float ov[KNN]; int oi[KNN];
#pragma unroll
            for (int m = 0; m < KNN; ++m) {
                ov[m] = __shfl_xor_sync(0xffffffffu, tv[li][m], off);
                oi[m] = __shfl_xor_sync(0xffffffffu, ti[li][m], off);
            }
#pragma unroll
            for (int m = 0; m < KNN; ++m)
                if (knn_better(ov[m], oi[m], tv[li][0], ti[li][0]))
                    topk_insert5(tv[li], ti[li], ov[m], oi[m]);
        }
    }
    // q==0 lanes publish one list per (row, wn)
    float* rmv = (float*)(smem + SM_RMV);
    int*   rmi = (int*)(smem + SM_RMI);
    if (q == 0) {
#pragma unroll
        for (int mb = 0; mb < 2; ++mb)
#pragma unroll
            for (int rr = 0; rr < 2; ++rr) {
                const int li  = mb * 2 + rr;
                const int row = wm * 32 + mb * 16 + rr * 8 + g;
                const int base = (wn * 128 + row) * KNN;
#pragma unroll
                for (int m = 0; m < KNN; ++m) { rmv[base + m] = tv[li][m]; rmi[base + m] = ti[li][m]; }
            }
    }
    __syncthreads();

    // ---- col-side scan from T (J>I): LDS.128, 4 interleaved lists ----
    const int colX = tid & 127;
    const int half = tid >> 7;
    float cv[4][KNN]; int ci[4][KNN];
    if (J > I) {
#pragma unroll
        for (int l = 0; l < 4; ++l)
#pragma unroll
            for (int m = 0; m < KNN; ++m) { cv[l][m] = NEG_INF; ci[l][m] = 0x7fffffff; }
        const float sbj = sqB[colX];
        const float4* T4 = (const float4*)(T + colX * TSTRIDE + half * 64);
        const float4* A4 = (const float4*)(sqA + half * 64);
        const int gib = row0 + half * 64;
#pragma unroll
        for (int k = 0; k < 16; ++k) {
            const float4 f = T4[k];
            const float4 a = A4[k];
            const int gi = gib + k * 4;
            const float d0 = (2.f * f.x - sbj) - a.x;
            const float d1 = (2.f * f.y - sbj) - a.y;
            const float d2 = (2.f * f.z - sbj) - a.z;
            const float d3 = (2.f * f.w - sbj) - a.w;
            if (d0 > cv[0][0]) topk_insert5_gt(cv[0], ci[0], d0, gi);
            if (d1 > cv[1][0]) topk_insert5_gt(cv[1], ci[1], d1, gi + 1);
            if (d2 > cv[2][0]) topk_insert5_gt(cv[2], ci[2], d2, gi + 2);
            if (d3 > cv[3][0]) topk_insert5_gt(cv[3], ci[3], d3, gi + 3);
        }
        // merge the 4 interleaved lists (indices interleave -> full tie-break)
#pragma unroll
        for (int l = 1; l < 4; ++l)
#pragma unroll
            for (int m = 0; m < KNN; ++m)
                if (knn_better(cv[l][m], ci[l][m], cv[0][0], ci[0][0]))
                    topk_insert5(cv[0], ci[0], cv[l][m], ci[l][m]);
        // half==1 publishes its list
        if (half) {
            float* clv = (float*)(smem + SM_CLV);
            int*   cli = (int*)(smem + SM_CLI);
#pragma unroll
            for (int m = 0; m < KNN; ++m) { clv[colX * KNN + m] = cv[0][m]; cli[colX * KNN + m] = ci[0][m]; }
        }
    }

    // ---- row final merge: 2 lists per row (tid < 128) ----
    if (tid < 128) {
        float mv[KNN]; int mi[KNN];
#pragma unroll
        for (int m = 0; m < KNN; ++m) { mv[m] = rmv[tid * KNN + m]; mi[m] = rmi[tid * KNN + m]; }
#pragma unroll
        for (int m = 0; m < KNN; ++m) {
            const float v = rmv[(128 + tid) * KNN + m];
            const int   j = rmi[(128 + tid) * KNN + m];
            if (knn_better(v, j, mv[0], mi[0])) topk_insert5(mv, mi, v, j);
        }
        const size_t base = ((size_t)(row0 + tid) * NSLOT + J) * KNN;
#pragma unroll
        for (int m = 0; m < KNN; ++m) { g_topv[base + m] = mv[m]; g_topi[base + m] = mi[m]; }
    }

    // ---- col final merge: half0 merges half1's list, writes slot I ----
    if (J > I) {
        __syncthreads();
        if (!half) {
            const float* clv = (const float*)(smem + SM_CLV);
            const int*   cli = (const int*)(smem + SM_CLI);
#pragma unroll
            for (int m = 0; m < KNN; ++m) {
                const float v = clv[colX * KNN + m];
                const int   j = cli[colX * KNN + m];
                if (knn_better(v, j, cv[0][0], ci[0][0])) topk_insert5(cv[0], ci[0], v, j);
            }
            const size_t base = ((size_t)(col0 + colX) * NSLOT + I) * KNN;
#pragma unroll
            for (int m = 0; m < KNN; ++m) { g_topv[base + m] = cv[0][m]; g_topi[base + m] = ci[0][m]; }
        }
    }
}

// ======================= parallel merge (warp per row) + symmetric scatter ============
__global__ void merge_scatter_kernel(float* __restrict__ out, int N) {
    const int wid  = threadIdx.x >> 5;
    const int lane = threadIdx.x & 31;
    const int row  = blockIdx.x * 8 + wid;
    if (row >= N) return;

    float mv[KNN]; int mi[KNN];
#pragma unroll
    for (int m = 0; m < KNN; ++m) { mv[m] = NEG_INF; mi[m] = 0x7fffffff; }

    const size_t base0 = (size_t)row * NSLOT * KNN;
    for (int s = lane; s < NSLOT; s += 32) {
#pragma unroll
        for (int m = 0; m < KNN; ++m) {
            float v = g_topv[base0 + s * KNN + m];
            int   j = g_topi[base0 + s * KNN + m];
            if (j < N && knn_better(v, j, mv[0], mi[0])) topk_insert5(mv, mi, v, j);
        }
    }
#pragma unroll
    for (int off = 16; off > 0; off >>= 1) {
        float ov[KNN]; int oi[KNN];
#pragma unroll
        for (int m = 0; m < KNN; ++m) {
            ov[m] = __shfl_down_sync(0xffffffffu, mv[m], off);
            oi[m] = __shfl_down_sync(0xffffffffu, mi[m], off);
        }
        if (lane < off) {
#pragma unroll
            for (int m = 0; m < KNN; ++m)
                if (oi[m] < N && knn_better(ov[m], oi[m], mv[0], mi[0]))
                    topk_insert5(mv, mi, ov[m], oi[m]);
        }
    }
    if (lane == 0) {
#pragma unroll
        for (int m = 0; m < KNN; ++m) {
            const int j = mi[m]; const float v = mv[m];
            if (j < N && j != row) {
                atomicAdd(out + (size_t)row * N + j, v);
                atomicAdd(out + (size_t)j * N + row, v);
            }
        }
    }
}

// ======================= launch =======================
extern "C" void kernel_launch(void* const* d_in, const int* in_sizes, int n_in,
                              void* d_out, int out_size) {
    const float* x = (const float*)d_in[0];
    const int N = in_sizes[0] / D_FEAT;   // 10000 here (<= NPADR)
    float* out = (float*)d_out;

    cudaFuncSetAttribute(gemm_knn_kernel, cudaFuncAttributeMaxDynamicSharedMemorySize, SMEM_DYN);

    prep_kernel<<<(NPADR * 16 + 255) / 256, 256>>>(x, N);
    gemm_knn_kernel<<<NPAIR, TPB, SMEM_DYN>>>(out, N);
    merge_scatter_kernel<<<(N + 7) / 8, 256>>>(out, N);
}

// round 12
// speedup vs baseline: 1.6093x; 1.0926x over previous
#include <cuda_runtime.h>
#include <cuda_fp16.h>
#include <cstdint>

// ======================= constants =======================
#define D_FEAT  64
#define KNN     5
#define KH      192            // 3 x 64 fp16 (hi/lo cross-term expansion)
#define TPB     256
#define NB      79             // number of 128-row blocks
#define NPAIR   (NB * (NB + 1) / 2)   // 3160 upper-triangular block pairs
#define NPADR   (NB * 128)     // 10112
#define MS      80             // row stride of the tile-max matrix M
#define NSLOT2  16             // phase-2 result slots per row
#define MAXT    4096           // max phase-2 tasks per column block
#define NEG_INF (-3.402823466e38f)
#define PAD_SQ  1.0e30f        // padded-row norm -> d ~ -1e30, never selected

// smem layout (bytes): row stride 400 (200 halfs) -> ldmatrix conflict-free
#define SAB      400
#define SM_A     0            // 128 x 400 = 51200
#define SM_B     51200        // 128 x 400 = 51200
#define SM_SQA   102400       // 128 floats
#define SM_SQB   102912       // 128 floats
#define SMEM_DYN 103424
// epilogue overlays (A/B tile region reused after the MMA):
#define TSTRIDE  132          // words; 16B-aligned rows, conflict-free col scans
#define SM_T     0            // 128 cols x 132 x 4 = 67584
#define SM_RM    67584        // row maxes: 2 x 128 floats = 1024
#define SM_CM    68608        // col maxes: 128 floats = 512

// ======================= device scratch (static; no allocs) =======================
__device__ __half g_xa[(size_t)NPADR * KH];   // [hi, lo, hi]
__device__ __half g_xb[(size_t)NPADR * KH];   // [hi, hi, lo]
__device__ float  g_sq[NPADR];
__device__ float  g_M[(size_t)NPADR * MS];    // per-(row, block) max distance
__device__ int    g_rowcnt[NPADR];
__device__ int    g_blkcnt[NB];
__device__ int    g_blkrows[(size_t)NB * MAXT];   // (row << 4) | slot
__device__ float  g_topv[(size_t)NPADR * NSLOT2 * KNN];
__device__ int    g_topi[(size_t)NPADR * NSLOT2 * KNN];

// ======================= baseline-ISA PTX helpers (NO tcgen05) =======================
__device__ __forceinline__ uint32_t smem_to_u32(const void* p) {
    uint32_t a;
    asm("{ .reg .u64 t; cvta.to.shared.u64 t, %1; cvt.u32.u64 %0, t; }" : "=r"(a) : "l"(p));
    return a;
}
__device__ __forceinline__ void cp16(uint32_t dst, const void* src) {
    asm volatile("cp.async.cg.shared.global [%0], [%1], 16;" :: "r"(dst), "l"(src));
}
#define CP_COMMIT() asm volatile("cp.async.commit_group;" ::: "memory")
#define CP_WAIT(n)  asm volatile("cp.async.wait_group %0;" :: "n"(n) : "memory")

__device__ __forceinline__ void ldsm_x4(uint32_t* r, uint32_t addr) {
    asm volatile("ldmatrix.sync.aligned.m8n8.x4.shared.b16 {%0,%1,%2,%3}, [%4];"
                 : "=r"(r[0]), "=r"(r[1]), "=r"(r[2]), "=r"(r[3]) : "r"(addr));
}
__device__ __forceinline__ void mma16816(float* c, const uint32_t* a, const uint32_t* b) {
    asm volatile("mma.sync.aligned.m16n8k16.row.col.f32.f16.f16.f32 "
                 "{%0,%1,%2,%3}, {%4,%5,%6,%7}, {%8,%9}, {%0,%1,%2,%3};"
                 : "+f"(c[0]), "+f"(c[1]), "+f"(c[2]), "+f"(c[3])
                 : "r"(a[0]), "r"(a[1]), "r"(a[2]), "r"(a[3]), "r"(b[0]), "r"(b[1]));
}

// ======================= top-k =======================
__device__ __forceinline__ bool knn_better(float v, int i, float v2, int i2) {
    return (v > v2) || (v == v2 && i < i2);
}
__device__ __forceinline__ void topk_insert5(float* tv, int* ti, float v, int i) {
    bool cont = true;
#pragma unroll
    for (int s = 0; s < KNN; ++s) {
        bool up = (s < KNN - 1) && knn_better(v, i, tv[s + 1], ti[s + 1]);
        if (cont) {
            if (up) { tv[s] = tv[s + 1]; ti[s] = ti[s + 1]; }
            else    { tv[s] = v;          ti[s] = i; cont = false; }
        }
    }
}

// ======================= prep: fp16 split + norms + counter/slot init ================
__global__ void prep_kernel(const float* __restrict__ x, int N) {
    const int idx = blockIdx.x * blockDim.x + threadIdx.x;
    if (idx >= NPADR * 16) return;
    const int i  = idx >> 4;
    const int kq = idx & 15;
    const int k  = kq * 4;

    // init phase-2 slot indices (idx enumerates (row, slot) exactly) + counters
    {
        int* tb = g_topi + (size_t)idx * KNN;
#pragma unroll
        for (int m = 0; m < KNN; ++m) tb[m] = 0x7fffffff;
    }
    if (kq == 0) g_rowcnt[i] = 0;
    if (idx < NB) g_blkcnt[idx] = 0;

    float4 v4 = make_float4(0.f, 0.f, 0.f, 0.f);
    if (i < N) v4 = *(const float4*)(x + (size_t)i * D_FEAT + k);

    __half h[4], l[4];
    const float vv[4] = {v4.x, v4.y, v4.z, v4.w};
    float psum = 0.f;
#pragma unroll
    for (int e = 0; e < 4; ++e) {
        psum += vv[e] * vv[e];
        h[e] = __float2half_rn(vv[e]);
        l[e] = __float2half_rn(vv[e] - __half2float(h[e]));
    }
    uint2 hp, lp;
    hp.x = __half_as_ushort(h[0]) | ((uint32_t)__half_as_ushort(h[1]) << 16);
    hp.y = __half_as_ushort(h[2]) | ((uint32_t)__half_as_ushort(h[3]) << 16);
    lp.x = __half_as_ushort(l[0]) | ((uint32_t)__half_as_ushort(l[1]) << 16);
    lp.y = __half_as_ushort(l[2]) | ((uint32_t)__half_as_ushort(l[3]) << 16);

    __half* a = g_xa + (size_t)i * KH;
    __half* b = g_xb + (size_t)i * KH;
    *(uint2*)(a + k)       = hp;   // A: [hi, lo, hi]
    *(uint2*)(a + 64 + k)  = lp;
    *(uint2*)(a + 128 + k) = hp;
    *(uint2*)(b + k)       = hp;   // B: [hi, hi, lo]
    *(uint2*)(b + 64 + k)  = hp;
    *(uint2*)(b + 128 + k) = lp;

#pragma unroll
    for (int s = 8; s > 0; s >>= 1) psum += __shfl_xor_sync(0xffffffffu, psum, s);
    if (kq == 0) g_sq[i] = (i < N) ? psum : PAD_SQ;
}

// ======================= phase 1: tile MMA -> per-(row, block) MAX only ===============
__global__ __launch_bounds__(TPB, 2)
void gemm_max_kernel(float* __restrict__ out, int N) {
    extern __shared__ __align__(16) char smem[];
    const uint32_t sb = smem_to_u32(smem);
    float* sqA = (float*)(smem + SM_SQA);
    float* sqB = (float*)(smem + SM_SQB);

    const int tid  = threadIdx.x;
    const int w    = tid >> 5;
    const int lane = tid & 31;
    const int wm   = w & 3;
    const int wn   = w >> 2;
    const int g    = lane >> 2;
    const int q    = lane & 3;

    // blockIdx.x -> upper-triangular pair (I, J)
    const int pg = blockIdx.x;
    int I;
    {
        const float s0 = 2.f * NB + 1.f;
        I = (int)((s0 - sqrtf(s0 * s0 - 8.f * (float)pg)) * 0.5f);
        if (I < 0) I = 0; if (I > NB - 1) I = NB - 1;
        while (I > 0 && (I * NB - ((I * (I - 1)) >> 1)) > pg) --I;
        while (I < NB - 1 && ((I + 1) * NB - (((I + 1) * I) >> 1)) <= pg) ++I;
    }
    const int J = I + (pg - (I * NB - ((I * (I - 1)) >> 1)));
    const int row0 = I * 128;
    const int col0 = J * 128;

    const uint32_t aAddr0 = sb + SM_A + (uint32_t)(wm * 32 + (lane & 15)) * SAB + ((lane >> 4) * 8) * 2;
    const uint32_t aAddr1 = aAddr0 + 16 * SAB;
    uint32_t bAddr[4];
#pragma unroll
    for (int nb2 = 0; nb2 < 4; ++nb2)
        bAddr[nb2] = sb + SM_B + (uint32_t)(wn * 64 + nb2 * 16 + ((lane >> 4) << 3) + (lane & 7)) * SAB
                     + (((lane >> 3) & 1) * 8) * 2;

    for (int idx = tid; idx < 128 * 24; idx += TPB) {
        int r = idx / 24, c = idx - r * 24;
        cp16(sb + SM_A + (uint32_t)r * SAB + c * 16,
             (const char*)(g_xa + (size_t)(row0 + r) * KH) + c * 16);
    }
    for (int idx = tid; idx < 128 * 24; idx += TPB) {
        int r = idx / 24, c = idx - r * 24;
        cp16(sb + SM_B + (uint32_t)r * SAB + c * 16,
             (const char*)(g_xb + (size_t)(col0 + r) * KH) + c * 16);
    }
    if (tid < 128) sqA[tid] = g_sq[row0 + tid];
    else           sqB[tid - 128] = g_sq[col0 + tid - 128];
    CP_COMMIT();

    // zero this CTA's slice of the 400MB output while loads are in flight
    {
        const unsigned Z   = (unsigned)N * (unsigned)N;
        const unsigned per = (((Z + NPAIR - 1u) / NPAIR) + 3u) & ~3u;
        const unsigned lo  = (unsigned)pg * per;
        unsigned hi = lo + per; if (hi > Z) hi = Z;
        if (hi > lo) {
            float4* o4 = (float4*)(out + lo);
            const unsigned n4 = (hi - lo) >> 2;
            const float4 zz = make_float4(0.f, 0.f, 0.f, 0.f);
#pragma unroll 4
            for (unsigned i4 = tid; i4 < n4; i4 += TPB) __stcs(o4 + i4, zz);
            const unsigned tail = lo + (n4 << 2);
            if ((unsigned)tid < (hi - tail)) __stcs(out + tail + tid, 0.f);
        }
    }

    CP_WAIT(0);
    __syncthreads();

    // ---- 128x128x192 mainloop ----
    float c[2][8][4];
#pragma unroll
    for (int mb = 0; mb < 2; ++mb)
#pragma unroll
        for (int nb = 0; nb < 8; ++nb)
#pragma unroll
            for (int e = 0; e < 4; ++e) c[mb][nb][e] = 0.f;

#pragma unroll
    for (int ks = 0; ks < 12; ++ks) {
        uint32_t a0[4], a1[4], b[4][4];
        ldsm_x4(a0, aAddr0 + ks * 32);
        ldsm_x4(a1, aAddr1 + ks * 32);
#pragma unroll
        for (int nb2 = 0; nb2 < 4; ++nb2) ldsm_x4(b[nb2], bAddr[nb2] + ks * 32);
#pragma unroll
        for (int nb2 = 0; nb2 < 4; ++nb2) {
            mma16816(c[0][nb2 * 2],     a0, &b[nb2][0]);
            mma16816(c[0][nb2 * 2 + 1], a0, &b[nb2][2]);
            mma16816(c[1][nb2 * 2],     a1, &b[nb2][0]);
            mma16816(c[1][nb2 * 2 + 1], a1, &b[nb2][2]);
        }
    }

    __syncthreads();   // ldsm reads done -> T overlay safe

    // ---- store RAW dot to T for the column pass ----
    float* T = (float*)(smem + SM_T);
    if (J > I) {
#pragma unroll
        for (int mb = 0; mb < 2; ++mb)
#pragma unroll
            for (int nb = 0; nb < 8; ++nb)
#pragma unroll
                for (int rr = 0; rr < 2; ++rr)
#pragma unroll
                    for (int e0 = 0; e0 < 2; ++e0) {
                        const int cl = wn * 64 + nb * 8 + q * 2 + e0;
                        const int rl = wm * 32 + mb * 16 + rr * 8 + g;
                        T[cl * TSTRIDE + rl] = c[mb][nb][rr * 2 + e0];
                    }
    }

    // ---- transform c in place: d = (2*dot - sa) - sb (row convention) ----
    float sa0[4];
#pragma unroll
    for (int mb = 0; mb < 2; ++mb)
#pragma unroll
        for (int rr = 0; rr < 2; ++rr)
            sa0[mb * 2 + rr] = sqA[wm * 32 + mb * 16 + rr * 8 + g];
#pragma unroll
    for (int nb = 0; nb < 8; ++nb)
#pragma unroll
        for (int e0 = 0; e0 < 2; ++e0) {
            const float sb_ = sqB[wn * 64 + nb * 8 + q * 2 + e0];
#pragma unroll
            for (int mb = 0; mb < 2; ++mb)
#pragma unroll
                for (int rr = 0; rr < 2; ++rr)
                    c[mb][nb][rr * 2 + e0] =
                        fmaf(c[mb][nb][rr * 2 + e0], 2.f, -sa0[mb * 2 + rr]) - sb_;
        }

    // ---- row MAX (pure FMNMX, no lists) ----
    float rm[4] = {NEG_INF, NEG_INF, NEG_INF, NEG_INF};
#pragma unroll
    for (int nb = 0; nb < 8; ++nb)
#pragma unroll
        for (int e0 = 0; e0 < 2; ++e0)
#pragma unroll
            for (int li = 0; li < 4; ++li)
                rm[li] = fmaxf(rm[li], c[li >> 1][nb][(li & 1) * 2 + e0]);
#pragma unroll
    for (int off = 1; off <= 2; off <<= 1)
#pragma unroll
        for (int li = 0; li < 4; ++li)
            rm[li] = fmaxf(rm[li], __shfl_xor_sync(0xffffffffu, rm[li], off));
    float* rowmaxs = (float*)(smem + SM_RM);
    if (q == 0) {
#pragma unroll
        for (int li = 0; li < 4; ++li) {
            const int rl = wm * 32 + (li >> 1) * 16 + (li & 1) * 8 + g;
            rowmaxs[wn * 128 + rl] = rm[li];
        }
    }
    __syncthreads();
    if (tid < 128)
        g_M[(size_t)(row0 + tid) * MS + J] = fmaxf(rowmaxs[tid], rowmaxs[128 + tid]);

    // ---- column MAX from T (off-diagonal tiles) ----
    if (J > I) {
        const int colX = tid & 127;
        const int half = tid >> 7;
        const float sbj = sqB[colX];
        float cm = NEG_INF;
        const float4* T4 = (const float4*)(T + colX * TSTRIDE + half * 64);
        const float4* A4 = (const float4*)(sqA + half * 64);
#pragma unroll
        for (int k = 0; k < 16; ++k) {
            const float4 f = T4[k];
            const float4 a = A4[k];
            cm = fmaxf(cm, (2.f * f.x - sbj) - a.x);
            cm = fmaxf(cm, (2.f * f.y - sbj) - a.y);
            cm = fmaxf(cm, (2.f * f.z - sbj) - a.z);
            cm = fmaxf(cm, (2.f * f.w - sbj) - a.w);
        }
        float* colmax = (float*)(smem + SM_CM);
        if (half) colmax[colX] = cm;
        __syncthreads();
        if (!half)
            g_M[(size_t)(col0 + colX) * MS + I] = fmaxf(cm, colmax[colX]);
    }
}

// ======================= phase 1.5: per-row tau + task building =======================
__global__ void select_kernel(int N) {
    const int wid  = threadIdx.x >> 5;
    const int lane = threadIdx.x & 31;
    const int row  = blockIdx.x * 8 + wid;
    if (row >= N) return;

    const float* Mr = g_M + (size_t)row * MS;
    float mv[KNN]; int mi[KNN];
#pragma unroll
    for (int m = 0; m < KNN; ++m) { mv[m] = NEG_INF; mi[m] = 0x7fffffff; }
    for (int s = lane; s < NB; s += 32) {
        const float v = Mr[s];
        if (knn_better(v, s, mv[0], mi[0])) topk_insert5(mv, mi, v, s);
    }
#pragma unroll
    for (int off = 16; off > 0; off >>= 1) {
        float ov[KNN]; int oi[KNN];
#pragma unroll
        for (int m = 0; m < KNN; ++m) {
            ov[m] = __shfl_down_sync(0xffffffffu, mv[m], off);
            oi[m] = __shfl_down_sync(0xffffffffu, mi[m], off);
        }
        if (lane < off) {
#pragma unroll
            for (int m = 0; m < KNN; ++m)
                if (oi[m] < NB && knn_better(ov[m], oi[m], mv[0], mi[0]))
                    topk_insert5(mv, mi, ov[m], oi[m]);
        }
    }
    const float tau = __shfl_sync(0xffffffffu, mv[0], 0);   // 5th-largest tile max
    for (int s = lane; s < NB; s += 32) {
        if (Mr[s] >= tau) {
            const int slot = atomicAdd(&g_rowcnt[row], 1);
            if (slot < NSLOT2) {
                const int pos = atomicAdd(&g_blkcnt[s], 1);
                if (pos < MAXT) g_blkrows[(size_t)s * MAXT + pos] = (row << 4) | slot;
            }
        }
    }
}

// ======================= phase 2: exact fp32 top-5 on selected (row, block) ==========
#define XS_STRIDE 76   // words per column: float4 phases hit 8 distinct bank groups
__global__ __launch_bounds__(256)
void refine_kernel(const float* __restrict__ x, int N) {
    __shared__ float xs[128 * XS_STRIDE];   // 38912 B
    __shared__ float sqs[128];

    const int b    = blockIdx.x;
    const int sub  = blockIdx.y;
    const int tid  = threadIdx.x;
    const int wid  = tid >> 5;
    const int lane = tid & 31;
    const int c0   = b * 128;

    for (int idx = tid; idx < 128 * D_FEAT; idx += 256) {
        const int j = idx >> 6, k = idx & 63;
        const int cg = c0 + j;
        xs[j * XS_STRIDE + k] = (cg < N) ? x[(size_t)cg * D_FEAT + k] : 0.f;
    }
    if (tid < 128) sqs[tid] = g_sq[c0 + tid];
    __syncthreads();

    int cnt = g_blkcnt[b]; if (cnt > MAXT) cnt = MAXT;
    for (int t = sub * 8 + wid; t < cnt; t += 64) {
        const int task = g_blkrows[(size_t)b * MAXT + t];
        const int row  = task >> 4;
        const int slot = task & 15;
        const float sa = g_sq[row];
        const float* xr = x + (size_t)row * D_FEAT;

        // each lane: 4 columns (lane, +32, +64, +96)
        float dot[4] = {0.f, 0.f, 0.f, 0.f};
#pragma unroll
        for (int f4 = 0; f4 < 16; ++f4) {
            const float4 xv = __ldg((const float4*)(xr + f4 * 4));
#pragma unroll
            for (int cc = 0; cc < 4; ++cc) {
                const float4 ys = *(const float4*)(xs + (lane + cc * 32) * XS_STRIDE + f4 * 4);
                dot[cc] = fmaf(xv.x, ys.x, dot[cc]);
                dot[cc] = fmaf(xv.y, ys.y, dot[cc]);
                dot[cc] = fmaf(xv.z, ys.z, dot[cc]);
                dot[cc] = fmaf(xv.w, ys.w, dot[cc]);
            }
        }
        float mv[KNN]; int mi[KNN];
#pragma unroll
        for (int m = 0; m < KNN; ++m) { mv[m] = NEG_INF; mi[m] = 0x7fffffff; }
#pragma unroll
        for (int cc = 0; cc < 4; ++cc) {
            const int cl = lane + cc * 32;
            const float d = fmaf(dot[cc], 2.f, -sa) - sqs[cl];
            topk_insert5(mv, mi, d, c0 + cl);
        }
#pragma unroll
        for (int off = 16; off > 0; off >>= 1) {
            float ov[KNN]; int oi[KNN];
#pragma unroll
            for (int m = 0; m < KNN; ++m) {
                ov[m] = __shfl_down_sync(0xffffffffu, mv[m], off);
                oi[m] = __shfl_down_sync(0xffffffffu, mi[m], off);
            }
            if (lane < off) {
#pragma unroll
                for (int m = 0; m < KNN; ++m)
                    if (knn_better(ov[m], oi[m], mv[0], mi[0]))
                        topk_insert5(mv, mi, ov[m], oi[m]);
            }
        }
        if (lane == 0) {
            const size_t base = ((size_t)row * NSLOT2 + slot) * KNN;
#pragma unroll
            for (int m = 0; m < KNN; ++m) { g_topv[base + m] = mv[m]; g_topi[base + m] = mi[m]; }
        }
    }
}

// ======================= final merge (warp per row) + symmetric scatter ==============
__global__ void merge_scatter_kernel(float* __restrict__ out, int N) {
    const int wid  = threadIdx.x >> 5;
    const int lane = threadIdx.x & 31;
    const int row  = blockIdx.x * 8 + wid;
    if (row >= N) return;

    float mv[KNN]; int mi[KNN];
#pragma unroll
    for (int m = 0; m < KNN; ++m) { mv[m] = NEG_INF; mi[m] = 0x7fffffff; }

    const size_t base0 = (size_t)row * NSLOT2 * KNN;
    if (lane < NSLOT2) {
#pragma unroll
        for (int m = 0; m < KNN; ++m) {
            const float v = g_topv[base0 + lane * KNN + m];
            const int   j = g_topi[base0 + lane * KNN + m];
            if (j < N && knn_better(v, j, mv[0], mi[0])) topk_insert5(mv, mi, v, j);
        }
    }
#pragma unroll
    for (int off = 16; off > 0; off >>= 1) {
        float ov[KNN]; int oi[KNN];
#pragma unroll
        for (int m = 0; m < KNN; ++m) {
            ov[m] = __shfl_down_sync(0xffffffffu, mv[m], off);
            oi[m] = __shfl_down_sync(0xffffffffu, mi[m], off);
        }
        if (lane < off) {
#pragma unroll
            for (int m = 0; m < KNN; ++m)
                if (oi[m] < N && knn_better(ov[m], oi[m], mv[0], mi[0]))
                    topk_insert5(mv, mi, ov[m], oi[m]);
        }
    }
    // self (d~0) is the row max; reference zeroes the diagonal -> skip j == row.
    if (lane == 0) {
#pragma unroll
        for (int m = 0; m < KNN; ++m) {
            const int j = mi[m]; const float v = mv[m];
            if (j < N && j != row) {
                atomicAdd(out + (size_t)row * N + j, v);
                atomicAdd(out + (size_t)j * N + row, v);
            }
        }
    }
}

// ======================= launch =======================
extern "C" void kernel_launch(void* const* d_in, const int* in_sizes, int n_in,
                              void* d_out, int out_size) {
    const float* x = (const float*)d_in[0];
    const int N = in_sizes[0] / D_FEAT;   // 10000 here (<= NPADR)
    float* out = (float*)d_out;

    cudaFuncSetAttribute(gemm_max_kernel, cudaFuncAttributeMaxDynamicSharedMemorySize, SMEM_DYN);

    prep_kernel<<<(NPADR * 16 + 255) / 256, 256>>>(x, N);
    gemm_max_kernel<<<NPAIR, TPB, SMEM_DYN>>>(out, N);
    select_kernel<<<(N + 7) / 8, 256>>>(N);
    dim3 g2(NB, 8);
    refine_kernel<<<g2, 256>>>(x, N);
    merge_scatter_kernel<<<(N + 7) / 8, 256>>>(out, N);
}

// round 13
// speedup vs baseline: 1.9670x; 1.2223x over previous
#include <cuda_runtime.h>
#include <cuda_fp16.h>
#include <cstdint>

// ======================= constants =======================
#define D_FEAT  64
#define KNN     5
#define KH      192            // 3 x 64 fp16 (hi/lo cross-term expansion)
#define TPB     256
#define NB      79             // number of 128-row blocks
#define NPAIR   (NB * (NB + 1) / 2)   // 3160 upper-triangular block pairs
#define NPADR   (NB * 128)     // 10112
#define MS      80             // row stride of the tile-max matrix M
#define NSLOT2  16             // phase-2 result slots per row
#define MAXT    4096           // max phase-2 tasks per column block
#define NEG_INF (-3.402823466e38f)
#define PAD_SQ  1.0e30f        // padded-row norm -> d ~ -1e30, never selected
#define TAU_MARGIN 0.01f       // covers MMA<->fp32 distance discrepancy (<=1e-4)

// smem layout (bytes): row stride 400 (200 halfs) -> ldmatrix conflict-free
#define SAB      400
#define SM_A     0            // 128 x 400 = 51200
#define SM_B     51200        // 128 x 400 = 51200
#define SM_SQA   102400       // 128 floats
#define SM_SQB   102912       // 128 floats
#define SMEM_DYN 103424
// epilogue overlays (A/B tile region reused after the MMA):
#define TSTRIDE  132          // words; 16B-aligned rows, conflict-free col scans
#define SM_T     0            // 128 cols x 132 x 4 = 67584
#define SM_RM    67584        // row maxes: 2 x 128 floats = 1024
#define SM_CM    68608        // col maxes: 128 floats = 512

// ======================= device scratch (static; no allocs) =======================
__device__ __half g_xa[(size_t)NPADR * KH];   // [hi, lo, hi]
__device__ __half g_xb[(size_t)NPADR * KH];   // [hi, hi, lo]
__device__ float  g_sq[NPADR];
__device__ float  g_M[(size_t)NPADR * MS];    // per-(row, block) max distance
__device__ float  g_tau[NPADR];               // per-row 5th-largest tile max
__device__ int    g_rowcnt[NPADR];
__device__ int    g_blkcnt[NB];
__device__ int    g_blkrows[(size_t)NB * MAXT];   // (row << 4) | slot
__device__ float  g_topv[(size_t)NPADR * NSLOT2 * KNN];
__device__ int    g_topi[(size_t)NPADR * NSLOT2 * KNN];

// ======================= baseline-ISA PTX helpers (NO tcgen05) =======================
__device__ __forceinline__ uint32_t smem_to_u32(const void* p) {
    uint32_t a;
    asm("{ .reg .u64 t; cvta.to.shared.u64 t, %1; cvt.u32.u64 %0, t; }" : "=r"(a) : "l"(p));
    return a;
}
__device__ __forceinline__ void cp16(uint32_t dst, const void* src) {
    asm volatile("cp.async.cg.shared.global [%0], [%1], 16;" :: "r"(dst), "l"(src));
}
#define CP_COMMIT() asm volatile("cp.async.commit_group;" ::: "memory")
#define CP_WAIT(n)  asm volatile("cp.async.wait_group %0;" :: "n"(n) : "memory")

__device__ __forceinline__ void ldsm_x4(uint32_t* r, uint32_t addr) {
    asm volatile("ldmatrix.sync.aligned.m8n8.x4.shared.b16 {%0,%1,%2,%3}, [%4];"
                 : "=r"(r[0]), "=r"(r[1]), "=r"(r[2]), "=r"(r[3]) : "r"(addr));
}
__device__ __forceinline__ void mma16816(float* c, const uint32_t* a, const uint32_t* b) {
    asm volatile("mma.sync.aligned.m16n8k16.row.col.f32.f16.f16.f32 "
                 "{%0,%1,%2,%3}, {%4,%5,%6,%7}, {%8,%9}, {%0,%1,%2,%3};"
                 : "+f"(c[0]), "+f"(c[1]), "+f"(c[2]), "+f"(c[3])
                 : "r"(a[0]), "r"(a[1]), "r"(a[2]), "r"(a[3]), "r"(b[0]), "r"(b[1]));
}

// ======================= top-k =======================
__device__ __forceinline__ bool knn_better(float v, int i, float v2, int i2) {
    return (v > v2) || (v == v2 && i < i2);
}
__device__ __forceinline__ void topk_insert5(float* tv, int* ti, float v, int i) {
    bool cont = true;
#pragma unroll
    for (int s = 0; s < KNN; ++s) {
        bool up = (s < KNN - 1) && knn_better(v, i, tv[s + 1], ti[s + 1]);
        if (cont) {
            if (up) { tv[s] = tv[s + 1]; ti[s] = ti[s + 1]; }
            else    { tv[s] = v;          ti[s] = i; cont = false; }
        }
    }
}

// ======================= prep: fp16 split + norms + counter/slot init ================
__global__ void prep_kernel(const float* __restrict__ x, int N) {
    const int idx = blockIdx.x * blockDim.x + threadIdx.x;
    if (idx >= NPADR * 16) return;
    const int i  = idx >> 4;
    const int kq = idx & 15;
    const int k  = kq * 4;

    // init phase-2 slot indices (idx enumerates (row, slot) exactly) + counters
    {
        int* tb = g_topi + (size_t)idx * KNN;
#pragma unroll
        for (int m = 0; m < KNN; ++m) tb[m] = 0x7fffffff;
    }
    if (kq == 0) g_rowcnt[i] = 0;
    if (idx < NB) g_blkcnt[idx] = 0;

    float4 v4 = make_float4(0.f, 0.f, 0.f, 0.f);
    if (i < N) v4 = *(const float4*)(x + (size_t)i * D_FEAT + k);

    __half h[4], l[4];
    const float vv[4] = {v4.x, v4.y, v4.z, v4.w};
    float psum = 0.f;
#pragma unroll
    for (int e = 0; e < 4; ++e) {
        psum += vv[e] * vv[e];
        h[e] = __float2half_rn(vv[e]);
        l[e] = __float2half_rn(vv[e] - __half2float(h[e]));
    }
    uint2 hp, lp;
    hp.x = __half_as_ushort(h[0]) | ((uint32_t)__half_as_ushort(h[1]) << 16);
    hp.y = __half_as_ushort(h[2]) | ((uint32_t)__half_as_ushort(h[3]) << 16);
    lp.x = __half_as_ushort(l[0]) | ((uint32_t)__half_as_ushort(l[1]) << 16);
    lp.y = __half_as_ushort(l[2]) | ((uint32_t)__half_as_ushort(l[3]) << 16);

    __half* a = g_xa + (size_t)i * KH;
    __half* b = g_xb + (size_t)i * KH;
    *(uint2*)(a + k)       = hp;   // A: [hi, lo, hi]
    *(uint2*)(a + 64 + k)  = lp;
    *(uint2*)(a + 128 + k) = hp;
    *(uint2*)(b + k)       = hp;   // B: [hi, hi, lo]
    *(uint2*)(b + 64 + k)  = hp;
    *(uint2*)(b + 128 + k) = lp;

#pragma unroll
    for (int s = 8; s > 0; s >>= 1) psum += __shfl_xor_sync(0xffffffffu, psum, s);
    if (kq == 0) g_sq[i] = (i < N) ? psum : PAD_SQ;
}

// ======================= phase 1: tile MMA -> per-(row, block) MAX only ===============
__global__ __launch_bounds__(TPB, 2)
void gemm_max_kernel(float* __restrict__ out, int N) {
    extern __shared__ __align__(16) char smem[];
    const uint32_t sb = smem_to_u32(smem);
    float* sqA = (float*)(smem + SM_SQA);
    float* sqB = (float*)(smem + SM_SQB);

    const int tid  = threadIdx.x;
    const int w    = tid >> 5;
    const int lane = tid & 31;
    const int wm   = w & 3;
    const int wn   = w >> 2;
    const int g    = lane >> 2;
    const int q    = lane & 3;

    // blockIdx.x -> upper-triangular pair (I, J)
    const int pg = blockIdx.x;
    int I;
    {
        const float s0 = 2.f * NB + 1.f;
        I = (int)((s0 - sqrtf(s0 * s0 - 8.f * (float)pg)) * 0.5f);
        if (I < 0) I = 0; if (I > NB - 1) I = NB - 1;
        while (I > 0 && (I * NB - ((I * (I - 1)) >> 1)) > pg) --I;
        while (I < NB - 1 && ((I + 1) * NB - (((I + 1) * I) >> 1)) <= pg) ++I;
    }
    const int J = I + (pg - (I * NB - ((I * (I - 1)) >> 1)));
    const int row0 = I * 128;
    const int col0 = J * 128;

    const uint32_t aAddr0 = sb + SM_A + (uint32_t)(wm * 32 + (lane & 15)) * SAB + ((lane >> 4) * 8) * 2;
    const uint32_t aAddr1 = aAddr0 + 16 * SAB;
    uint32_t bAddr[4];
#pragma unroll
    for (int nb2 = 0; nb2 < 4; ++nb2)
        bAddr[nb2] = sb + SM_B + (uint32_t)(wn * 64 + nb2 * 16 + ((lane >> 4) << 3) + (lane & 7)) * SAB
                     + (((lane >> 3) & 1) * 8) * 2;

    for (int idx = tid; idx < 128 * 24; idx += TPB) {
        int r = idx / 24, c = idx - r * 24;
        cp16(sb + SM_A + (uint32_t)r * SAB + c * 16,
             (const char*)(g_xa + (size_t)(row0 + r) * KH) + c * 16);
    }
    for (int idx = tid; idx < 128 * 24; idx += TPB) {
        int r = idx / 24, c = idx - r * 24;
        cp16(sb + SM_B + (uint32_t)r * SAB + c * 16,
             (const char*)(g_xb + (size_t)(col0 + r) * KH) + c * 16);
    }
    if (tid < 128) sqA[tid] = g_sq[row0 + tid];
    else           sqB[tid - 128] = g_sq[col0 + tid - 128];
    CP_COMMIT();

    // zero this CTA's slice of the 400MB output while loads are in flight
    {
        const unsigned Z   = (unsigned)N * (unsigned)N;
        const unsigned per = (((Z + NPAIR - 1u) / NPAIR) + 3u) & ~3u;
        const unsigned lo  = (unsigned)pg * per;
        unsigned hi = lo + per; if (hi > Z) hi = Z;
        if (hi > lo) {
            float4* o4 = (float4*)(out + lo);
            const unsigned n4 = (hi - lo) >> 2;
            const float4 zz = make_float4(0.f, 0.f, 0.f, 0.f);
#pragma unroll 4
            for (unsigned i4 = tid; i4 < n4; i4 += TPB) __stcs(o4 + i4, zz);
            const unsigned tail = lo + (n4 << 2);
            if ((unsigned)tid < (hi - tail)) __stcs(out + tail + tid, 0.f);
        }
    }

    CP_WAIT(0);
    __syncthreads();

    // ---- 128x128x192 mainloop ----
    float c[2][8][4];
#pragma unroll
    for (int mb = 0; mb < 2; ++mb)
#pragma unroll
        for (int nb = 0; nb < 8; ++nb)
#pragma unroll
            for (int e = 0; e < 4; ++e) c[mb][nb][e] = 0.f;

#pragma unroll
    for (int ks = 0; ks < 12; ++ks) {
        uint32_t a0[4], a1[4], b[4][4];
        ldsm_x4(a0, aAddr0 + ks * 32);
        ldsm_x4(a1, aAddr1 + ks * 32);
#pragma unroll
        for (int nb2 = 0; nb2 < 4; ++nb2) ldsm_x4(b[nb2], bAddr[nb2] + ks * 32);
#pragma unroll
        for (int nb2 = 0; nb2 < 4; ++nb2) {
            mma16816(c[0][nb2 * 2],     a0, &b[nb2][0]);
            mma16816(c[0][nb2 * 2 + 1], a0, &b[nb2][2]);
            mma16816(c[1][nb2 * 2],     a1, &b[nb2][0]);
            mma16816(c[1][nb2 * 2 + 1], a1, &b[nb2][2]);
        }
    }

    __syncthreads();   // ldsm reads done -> T overlay safe

    // ---- store RAW dot to T for the column pass ----
    float* T = (float*)(smem + SM_T);
    if (J > I) {
#pragma unroll
        for (int mb = 0; mb < 2; ++mb)
#pragma unroll
            for (int nb = 0; nb < 8; ++nb)
#pragma unroll
                for (int rr = 0; rr < 2; ++rr)
#pragma unroll
                    for (int e0 = 0; e0 < 2; ++e0) {
                        const int cl = wn * 64 + nb * 8 + q * 2 + e0;
                        const int rl = wm * 32 + mb * 16 + rr * 8 + g;
                        T[cl * TSTRIDE + rl] = c[mb][nb][rr * 2 + e0];
                    }
    }

    // ---- transform c in place: d = (2*dot - sa) - sb (row convention) ----
    float sa0[4];
#pragma unroll
    for (int mb = 0; mb < 2; ++mb)
#pragma unroll
        for (int rr = 0; rr < 2; ++rr)
            sa0[mb * 2 + rr] = sqA[wm * 32 + mb * 16 + rr * 8 + g];
#pragma unroll
    for (int nb = 0; nb < 8; ++nb)
#pragma unroll
        for (int e0 = 0; e0 < 2; ++e0) {
            const float sb_ = sqB[wn * 64 + nb * 8 + q * 2 + e0];
#pragma unroll
            for (int mb = 0; mb < 2; ++mb)
#pragma unroll
                for (int rr = 0; rr < 2; ++rr)
                    c[mb][nb][rr * 2 + e0] =
                        fmaf(c[mb][nb][rr * 2 + e0], 2.f, -sa0[mb * 2 + rr]) - sb_;
        }

    // ---- row MAX (pure FMNMX, no lists) ----
    float rm[4] = {NEG_INF, NEG_INF, NEG_INF, NEG_INF};
#pragma unroll
    for (int nb = 0; nb < 8; ++nb)
#pragma unroll
        for (int e0 = 0; e0 < 2; ++e0)
#pragma unroll
            for (int li = 0; li < 4; ++li)
                rm[li] = fmaxf(rm[li], c[li >> 1][nb][(li & 1) * 2 + e0]);
#pragma unroll
    for (int off = 1; off <= 2; off <<= 1)
#pragma unroll
        for (int li = 0; li < 4; ++li)
            rm[li] = fmaxf(rm[li], __shfl_xor_sync(0xffffffffu, rm[li], off));
    float* rowmaxs = (float*)(smem + SM_RM);
    if (q == 0) {
#pragma unroll
        for (int li = 0; li < 4; ++li) {
            const int rl = wm * 32 + (li >> 1) * 16 + (li & 1) * 8 + g;
            rowmaxs[wn * 128 + rl] = rm[li];
        }
    }
    __syncthreads();
    if (tid < 128)
        g_M[(size_t)(row0 + tid) * MS + J] = fmaxf(rowmaxs[tid], rowmaxs[128 + tid]);

    // ---- column MAX from T (off-diagonal tiles) ----
    if (J > I) {
        const int colX = tid & 127;
        const int half = tid >> 7;
        const float sbj = sqB[colX];
        float cm = NEG_INF;
        const float4* T4 = (const float4*)(T + colX * TSTRIDE + half * 64);
        const float4* A4 = (const float4*)(sqA + half * 64);
#pragma unroll
        for (int k = 0; k < 16; ++k) {
            const float4 f = T4[k];
            const float4 a = A4[k];
            cm = fmaxf(cm, (2.f * f.x - sbj) - a.x);
            cm = fmaxf(cm, (2.f * f.y - sbj) - a.y);
            cm = fmaxf(cm, (2.f * f.z - sbj) - a.z);
            cm = fmaxf(cm, (2.f * f.w - sbj) - a.w);
        }
        float* colmax = (float*)(smem + SM_CM);
        if (half) colmax[colX] = cm;
        __syncthreads();
        if (!half)
            g_M[(size_t)(col0 + colX) * MS + I] = fmaxf(cm, colmax[colX]);
    }
}

// ======================= phase 1.5: per-row tau + task building =======================
__global__ void select_kernel(int N) {
    const int wid  = threadIdx.x >> 5;
    const int lane = threadIdx.x & 31;
    const int row  = blockIdx.x * 8 + wid;
    if (row >= N) return;

    const float* Mr = g_M + (size_t)row * MS;
    float mv[KNN]; int mi[KNN];
#pragma unroll
    for (int m = 0; m < KNN; ++m) { mv[m] = NEG_INF; mi[m] = 0x7fffffff; }
    for (int s = lane; s < NB; s += 32) {
        const float v = Mr[s];
        if (knn_better(v, s, mv[0], mi[0])) topk_insert5(mv, mi, v, s);
    }
#pragma unroll
    for (int off = 16; off > 0; off >>= 1) {
        float ov[KNN]; int oi[KNN];
#pragma unroll
        for (int m = 0; m < KNN; ++m) {
            ov[m] = __shfl_down_sync(0xffffffffu, mv[m], off);
            oi[m] = __shfl_down_sync(0xffffffffu, mi[m], off);
        }
        if (lane < off) {
#pragma unroll
            for (int m = 0; m < KNN; ++m)
                if (oi[m] < NB && knn_better(ov[m], oi[m], mv[0], mi[0]))
                    topk_insert5(mv, mi, ov[m], oi[m]);
        }
    }
    const float tau = __shfl_sync(0xffffffffu, mv[0], 0);   // 5th-largest tile max
    if (lane == 0) g_tau[row] = tau;
    for (int s = lane; s < NB; s += 32) {
        if (Mr[s] >= tau) {
            const int slot = atomicAdd(&g_rowcnt[row], 1);
            if (slot < NSLOT2) {
                const int pos = atomicAdd(&g_blkcnt[s], 1);
                if (pos < MAXT) g_blkrows[(size_t)s * MAXT + pos] = (row << 4) | slot;
            }
        }
    }
}

// ======================= phase 2: fp32 dots + tau-filter (no per-task top-k) =========
#define XS_STRIDE 76   // words per column: float4 phases hit 8 distinct bank groups
__global__ __launch_bounds__(256)
void refine_kernel(const float* __restrict__ x, int N) {
    __shared__ float xs[128 * XS_STRIDE];   // 38912 B
    __shared__ float sqs[128];

    const int b    = blockIdx.x;
    const int sub  = blockIdx.y;
    const int tid  = threadIdx.x;
    const int wid  = tid >> 5;
    const int lane = tid & 31;
    const int c0   = b * 128;

    for (int idx = tid; idx < 128 * D_FEAT; idx += 256) {
        const int j = idx >> 6, k = idx & 63;
        const int cg = c0 + j;
        xs[j * XS_STRIDE + k] = (cg < N) ? x[(size_t)cg * D_FEAT + k] : 0.f;
    }
    if (tid < 128) sqs[tid] = g_sq[c0 + tid];
    __syncthreads();

    const unsigned lmask = (1u << lane) - 1u;
    int cnt = g_blkcnt[b]; if (cnt > MAXT) cnt = MAXT;
    for (int t = sub * 8 + wid; t < cnt; t += 64) {
        const int task = g_blkrows[(size_t)b * MAXT + t];
        const int row  = task >> 4;
        const int slot = task & 15;
        const float sa = g_sq[row];
        const float tauP = g_tau[row] - TAU_MARGIN;
        const float* xr = x + (size_t)row * D_FEAT;

        // each lane: 4 columns (lane, +32, +64, +96)
        float dot[4] = {0.f, 0.f, 0.f, 0.f};
#pragma unroll
        for (int f4 = 0; f4 < 16; ++f4) {
            const float4 xv = __ldg((const float4*)(xr + f4 * 4));
#pragma unroll
            for (int cc = 0; cc < 4; ++cc) {
                const float4 ys = *(const float4*)(xs + (lane + cc * 32) * XS_STRIDE + f4 * 4);
                dot[cc] = fmaf(xv.x, ys.x, dot[cc]);
                dot[cc] = fmaf(xv.y, ys.y, dot[cc]);
                dot[cc] = fmaf(xv.z, ys.z, dot[cc]);
                dot[cc] = fmaf(xv.w, ys.w, dot[cc]);
            }
        }
        float d[4]; bool pr[4]; unsigned bl[4]; int boff[4]; int tot = 0;
#pragma unroll
        for (int cc = 0; cc < 4; ++cc) {
            d[cc] = fmaf(dot[cc], 2.f, -sa) - sqs[lane + cc * 32];
            pr[cc] = (d[cc] >= tauP);
            bl[cc] = __ballot_sync(0xffffffffu, pr[cc]);
            boff[cc] = tot;
            tot += __popc(bl[cc]);
        }
        const size_t sbase = ((size_t)row * NSLOT2 + slot) * KNN;
        if (tot <= KNN) {
            // direct ranked emission; remaining entries stay prep-invalidated
#pragma unroll
            for (int cc = 0; cc < 4; ++cc)
                if (pr[cc]) {
                    const int pos = boff[cc] + __popc(bl[cc] & lmask);
                    g_topv[sbase + pos] = d[cc];
                    g_topi[sbase + pos] = c0 + lane + cc * 32;
                }
        } else {
            // rare fallback: exact tile top-5 (tie-aware)
            float mv[KNN]; int mi[KNN];
#pragma unroll
            for (int m = 0; m < KNN; ++m) { mv[m] = NEG_INF; mi[m] = 0x7fffffff; }
#pragma unroll
            for (int cc = 0; cc < 4; ++cc)
                topk_insert5(mv, mi, d[cc], c0 + lane + cc * 32);
#pragma unroll
            for (int off = 16; off > 0; off >>= 1) {
                float ov[KNN]; int oi[KNN];
#pragma unroll
                for (int m = 0; m < KNN; ++m) {
                    ov[m] = __shfl_down_sync(0xffffffffu, mv[m], off);
                    oi[m] = __shfl_down_sync(0xffffffffu, mi[m], off);
                }
                if (lane < off) {
#pragma unroll
                    for (int m = 0; m < KNN; ++m)
                        if (knn_better(ov[m], oi[m], mv[0], mi[0]))
                            topk_insert5(mv, mi, ov[m], oi[m]);
                }
            }
            if (lane == 0) {
#pragma unroll
                for (int m = 0; m < KNN; ++m) { g_topv[sbase + m] = mv[m]; g_topi[sbase + m] = mi[m]; }
            }
        }
    }
}

// ======================= final merge (warp per row) + symmetric scatter ==============
__global__ void merge_scatter_kernel(float* __restrict__ out, int N) {
    const int wid  = threadIdx.x >> 5;
    const int lane = threadIdx.x & 31;
    const int row  = blockIdx.x * 8 + wid;
    if (row >= N) return;

    float mv[KNN]; int mi[KNN];
#pragma unroll
    for (int m = 0; m < KNN; ++m) { mv[m] = NEG_INF; mi[m] = 0x7fffffff; }

    const size_t base0 = (size_t)row * NSLOT2 * KNN;
    if (lane < NSLOT2) {
#pragma unroll
        for (int m = 0; m < KNN; ++m) {
            const float v = g_topv[base0 + lane * KNN + m];
            const int   j = g_topi[base0 + lane * KNN + m];
            if (j < N && knn_better(v, j, mv[0], mi[0])) topk_insert5(mv, mi, v, j);
        }
    }
#pragma unroll
    for (int off = 16; off > 0; off >>= 1) {
        float ov[KNN]; int oi[KNN];
#pragma unroll
        for (int m = 0; m < KNN; ++m) {
            ov[m] = __shfl_down_sync(0xffffffffu, mv[m], off);
            oi[m] = __shfl_down_sync(0xffffffffu, mi[m], off);
        }
        if (lane < off) {
#pragma unroll
            for (int m = 0; m < KNN; ++m)
                if (oi[m] < N && knn_better(ov[m], oi[m], mv[0], mi[0]))
                    topk_insert5(mv, mi, ov[m], oi[m]);
        }
    }
    // self (d~0) is the row max; reference zeroes the diagonal -> skip j == row.
    if (lane == 0) {
#pragma unroll
        for (int m = 0; m < KNN; ++m) {
            const int j = mi[m]; const float v = mv[m];
            if (j < N && j != row) {
                atomicAdd(out + (size_t)row * N + j, v);
                atomicAdd(out + (size_t)j * N + row, v);
            }
        }
    }
}

// ======================= launch =======================
extern "C" void kernel_launch(void* const* d_in, const int* in_sizes, int n_in,
                              void* d_out, int out_size) {
    const float* x = (const float*)d_in[0];
    const int N = in_sizes[0] / D_FEAT;   // 10000 here (<= NPADR)
    float* out = (float*)d_out;

    cudaFuncSetAttribute(gemm_max_kernel, cudaFuncAttributeMaxDynamicSharedMemorySize, SMEM_DYN);

    prep_kernel<<<(NPADR * 16 + 255) / 256, 256>>>(x, N);
    gemm_max_kernel<<<NPAIR, TPB, SMEM_DYN>>>(out, N);
    select_kernel<<<(N + 7) / 8, 256>>>(N);
    dim3 g2(NB, 8);
    refine_kernel<<<g2, 256>>>(x, N);
    merge_scatter_kernel<<<(N + 7) / 8, 256>>>(out, N);
}

// round 14
// speedup vs baseline: 2.2970x; 1.1677x over previous
#include <cuda_runtime.h>
#include <cuda_fp16.h>
#include <cstdint>

// ======================= constants =======================
#define D_FEAT  64
#define KNN     5
#define KH      192            // 3 x 64 fp16 (hi/lo cross-term expansion)
#define TPB     256
#define NB      79             // number of 128-row blocks
#define NPAIR   (NB * (NB + 1) / 2)   // 3160 upper-triangular block pairs
#define NPADR   (NB * 128)     // 10112
#define MS      80             // row stride of the tile-max matrix M
#define NSLOT2  16             // phase-2 result slots per row
#define MAXT    4096           // max phase-2 tasks per column block
#define NEG_INF (-3.402823466e38f)
#define PAD_SQ  1.0e30f        // padded-row norm -> d ~ -1e30, never selected
#define TAU_MARGIN 0.01f       // covers MMA<->fp32 distance discrepancy (<=1e-4)

// smem layout (bytes): row stride 400 (200 halfs) -> ldmatrix conflict-free
#define SAB      400
#define SM_A     0            // 128 x 400 = 51200
#define SM_B     51200        // 128 x 400 = 51200
#define SM_SQA   102400       // 128 floats
#define SM_SQB   102912       // 128 floats
#define SMEM_DYN 103424
// epilogue overlays (A/B tile region reused after the MMA):
#define TSTRIDE  132          // words; 16B-aligned rows, conflict-free col scans
#define SM_T     0            // 128 cols x 132 x 4 = 67584
#define SM_RM    67584        // row maxes: 2 x 128 floats = 1024
#define SM_CM    68608        // col maxes: 128 floats = 512

// ======================= device scratch (static; no allocs) =======================
__device__ __half g_xa[(size_t)NPADR * KH];   // [hi, lo, hi]
__device__ __half g_xb[(size_t)NPADR * KH];   // [hi, hi, lo]
__device__ float  g_sq[NPADR];
__device__ float  g_M[(size_t)NPADR * MS];    // per-(row, block) max distance
__device__ float  g_tau[NPADR];               // per-row 5th-largest tile max
__device__ int    g_rowcnt[NPADR];
__device__ int    g_blkcnt[NB];
__device__ int    g_blkrows[(size_t)NB * MAXT];   // (row << 4) | slot
__device__ float  g_topv[(size_t)NPADR * NSLOT2 * KNN];
__device__ int    g_topi[(size_t)NPADR * NSLOT2 * KNN];

// ======================= baseline-ISA PTX helpers (NO tcgen05) =======================
__device__ __forceinline__ uint32_t smem_to_u32(const void* p) {
    uint32_t a;
    asm("{ .reg .u64 t; cvta.to.shared.u64 t, %1; cvt.u32.u64 %0, t; }" : "=r"(a) : "l"(p));
    return a;
}
__device__ __forceinline__ void cp16(uint32_t dst, const void* src) {
    asm volatile("cp.async.cg.shared.global [%0], [%1], 16;" :: "r"(dst), "l"(src));
}
#define CP_COMMIT() asm volatile("cp.async.commit_group;" ::: "memory")
#define CP_WAIT(n)  asm volatile("cp.async.wait_group %0;" :: "n"(n) : "memory")

__device__ __forceinline__ void ldsm_x4(uint32_t* r, uint32_t addr) {
    asm volatile("ldmatrix.sync.aligned.m8n8.x4.shared.b16 {%0,%1,%2,%3}, [%4];"
                 : "=r"(r[0]), "=r"(r[1]), "=r"(r[2]), "=r"(r[3]) : "r"(addr));
}
__device__ __forceinline__ void mma16816(float* c, const uint32_t* a, const uint32_t* b) {
    asm volatile("mma.sync.aligned.m16n8k16.row.col.f32.f16.f16.f32 "
                 "{%0,%1,%2,%3}, {%4,%5,%6,%7}, {%8,%9}, {%0,%1,%2,%3};"
                 : "+f"(c[0]), "+f"(c[1]), "+f"(c[2]), "+f"(c[3])
                 : "r"(a[0]), "r"(a[1]), "r"(a[2]), "r"(a[3]), "r"(b[0]), "r"(b[1]));
}

// ======================= top-k =======================
__device__ __forceinline__ bool knn_better(float v, int i, float v2, int i2) {
    return (v > v2) || (v == v2 && i < i2);
}
__device__ __forceinline__ void topk_insert5(float* tv, int* ti, float v, int i) {
    bool cont = true;
#pragma unroll
    for (int s = 0; s < KNN; ++s) {
        bool up = (s < KNN - 1) && knn_better(v, i, tv[s + 1], ti[s + 1]);
        if (cont) {
            if (up) { tv[s] = tv[s + 1]; ti[s] = ti[s + 1]; }
            else    { tv[s] = v;          ti[s] = i; cont = false; }
        }
    }
}

// ======================= prep: fp16 split + norms + counter/slot init ================
__global__ void prep_kernel(const float* __restrict__ x, int N) {
    const int idx = blockIdx.x * blockDim.x + threadIdx.x;
    if (idx >= NPADR * 16) return;
    const int i  = idx >> 4;
    const int kq = idx & 15;
    const int k  = kq * 4;

    // init phase-2 slot indices (idx enumerates (row, slot) exactly) + counters
    {
        int* tb = g_topi + (size_t)idx * KNN;
#pragma unroll
        for (int m = 0; m < KNN; ++m) tb[m] = 0x7fffffff;
    }
    if (kq == 0) g_rowcnt[i] = 0;
    if (idx < NB) g_blkcnt[idx] = 0;

    float4 v4 = make_float4(0.f, 0.f, 0.f, 0.f);
    if (i < N) v4 = *(const float4*)(x + (size_t)i * D_FEAT + k);

    __half h[4], l[4];
    const float vv[4] = {v4.x, v4.y, v4.z, v4.w};
    float psum = 0.f;
#pragma unroll
    for (int e = 0; e < 4; ++e) {
        psum += vv[e] * vv[e];
        h[e] = __float2half_rn(vv[e]);
        l[e] = __float2half_rn(vv[e] - __half2float(h[e]));
    }
    uint2 hp, lp;
    hp.x = __half_as_ushort(h[0]) | ((uint32_t)__half_as_ushort(h[1]) << 16);
    hp.y = __half_as_ushort(h[2]) | ((uint32_t)__half_as_ushort(h[3]) << 16);
    lp.x = __half_as_ushort(l[0]) | ((uint32_t)__half_as_ushort(l[1]) << 16);
    lp.y = __half_as_ushort(l[2]) | ((uint32_t)__half_as_ushort(l[3]) << 16);

    __half* a = g_xa + (size_t)i * KH;
    __half* b = g_xb + (size_t)i * KH;
    *(uint2*)(a + k)       = hp;   // A: [hi, lo, hi]
    *(uint2*)(a + 64 + k)  = lp;
    *(uint2*)(a + 128 + k) = hp;
    *(uint2*)(b + k)       = hp;   // B: [hi, hi, lo]
    *(uint2*)(b + 64 + k)  = hp;
    *(uint2*)(b + 128 + k) = lp;

#pragma unroll
    for (int s = 8; s > 0; s >>= 1) psum += __shfl_xor_sync(0xffffffffu, psum, s);
    if (kq == 0) g_sq[i] = (i < N) ? psum : PAD_SQ;
}

// ======================= phase 1: tile MMA -> per-(row, block) MAX only ===============
__global__ __launch_bounds__(TPB, 2)
void gemm_max_kernel(float* __restrict__ out, int N) {
    extern __shared__ __align__(16) char smem[];
    const uint32_t sb = smem_to_u32(smem);
    float* sqA = (float*)(smem + SM_SQA);
    float* sqB = (float*)(smem + SM_SQB);

    const int tid  = threadIdx.x;
    const int w    = tid >> 5;
    const int lane = tid & 31;
    const int wm   = w & 3;
    const int wn   = w >> 2;
    const int g    = lane >> 2;
    const int q    = lane & 3;

    // blockIdx.x -> upper-triangular pair (I, J)
    const int pg = blockIdx.x;
    int I;
    {
        const float s0 = 2.f * NB + 1.f;
        I = (int)((s0 - sqrtf(s0 * s0 - 8.f * (float)pg)) * 0.5f);
        if (I < 0) I = 0; if (I > NB - 1) I = NB - 1;
        while (I > 0 && (I * NB - ((I * (I - 1)) >> 1)) > pg) --I;
        while (I < NB - 1 && ((I + 1) * NB - (((I + 1) * I) >> 1)) <= pg) ++I;
    }
    const int J = I + (pg - (I * NB - ((I * (I - 1)) >> 1)));
    const int row0 = I * 128;
    const int col0 = J * 128;

    const uint32_t aAddr0 = sb + SM_A + (uint32_t)(wm * 32 + (lane & 15)) * SAB + ((lane >> 4) * 8) * 2;
    const uint32_t aAddr1 = aAddr0 + 16 * SAB;
    uint32_t bAddr[4];
#pragma unroll
    for (int nb2 = 0; nb2 < 4; ++nb2)
        bAddr[nb2] = sb + SM_B + (uint32_t)(wn * 64 + nb2 * 16 + ((lane >> 4) << 3) + (lane & 7)) * SAB
                     + (((lane >> 3) & 1) * 8) * 2;

    for (int idx = tid; idx < 128 * 24; idx += TPB) {
        int r = idx / 24, c = idx - r * 24;
        cp16(sb + SM_A + (uint32_t)r * SAB + c * 16,
             (const char*)(g_xa + (size_t)(row0 + r) * KH) + c * 16);
    }
    for (int idx = tid; idx < 128 * 24; idx += TPB) {
        int r = idx / 24, c = idx - r * 24;
        cp16(sb + SM_B + (uint32_t)r * SAB + c * 16,
             (const char*)(g_xb + (size_t)(col0 + r) * KH) + c * 16);
    }
    if (tid < 128) sqA[tid] = g_sq[row0 + tid];
    else           sqB[tid - 128] = g_sq[col0 + tid - 128];
    CP_COMMIT();

    // zero this CTA's slice of the 400MB output while loads are in flight
    {
        const unsigned Z   = (unsigned)N * (unsigned)N;
        const unsigned per = (((Z + NPAIR - 1u) / NPAIR) + 3u) & ~3u;
        const unsigned lo  = (unsigned)pg * per;
        unsigned hi = lo + per; if (hi > Z) hi = Z;
        if (hi > lo) {
            float4* o4 = (float4*)(out + lo);
            const unsigned n4 = (hi - lo) >> 2;
            const float4 zz = make_float4(0.f, 0.f, 0.f, 0.f);
#pragma unroll 4
            for (unsigned i4 = tid; i4 < n4; i4 += TPB) __stcs(o4 + i4, zz);
            const unsigned tail = lo + (n4 << 2);
            if ((unsigned)tid < (hi - tail)) __stcs(out + tail + tid, 0.f);
        }
    }

    CP_WAIT(0);
    __syncthreads();

    // ---- 128x128x192 mainloop ----
    float c[2][8][4];
#pragma unroll
    for (int mb = 0; mb < 2; ++mb)
#pragma unroll
        for (int nb = 0; nb < 8; ++nb)
#pragma unroll
            for (int e = 0; e < 4; ++e) c[mb][nb][e] = 0.f;

#pragma unroll
    for (int ks = 0; ks < 12; ++ks) {
        uint32_t a0[4], a1[4], b[4][4];
        ldsm_x4(a0, aAddr0 + ks * 32);
        ldsm_x4(a1, aAddr1 + ks * 32);
#pragma unroll
        for (int nb2 = 0; nb2 < 4; ++nb2) ldsm_x4(b[nb2], bAddr[nb2] + ks * 32);
#pragma unroll
        for (int nb2 = 0; nb2 < 4; ++nb2) {
            mma16816(c[0][nb2 * 2],     a0, &b[nb2][0]);
            mma16816(c[0][nb2 * 2 + 1], a0, &b[nb2][2]);
            mma16816(c[1][nb2 * 2],     a1, &b[nb2][0]);
            mma16816(c[1][nb2 * 2 + 1], a1, &b[nb2][2]);
        }
    }

    __syncthreads();   // ldsm reads done -> T overlay safe

    // ---- store RAW dot to T for the column pass ----
    float* T = (float*)(smem + SM_T);
    if (J > I) {
#pragma unroll
        for (int mb = 0; mb < 2; ++mb)
#pragma unroll
            for (int nb = 0; nb < 8; ++nb)
#pragma unroll
                for (int rr = 0; rr < 2; ++rr)
#pragma unroll
                    for (int e0 = 0; e0 < 2; ++e0) {
                        const int cl = wn * 64 + nb * 8 + q * 2 + e0;
                        const int rl = wm * 32 + mb * 16 + rr * 8 + g;
                        T[cl * TSTRIDE + rl] = c[mb][nb][rr * 2 + e0];
                    }
    }

    // ---- transform c in place: d = (2*dot - sa) - sb (row convention) ----
    float sa0[4];
#pragma unroll
    for (int mb = 0; mb < 2; ++mb)
#pragma unroll
        for (int rr = 0; rr < 2; ++rr)
            sa0[mb * 2 + rr] = sqA[wm * 32 + mb * 16 + rr * 8 + g];
#pragma unroll
    for (int nb = 0; nb < 8; ++nb)
#pragma unroll
        for (int e0 = 0; e0 < 2; ++e0) {
            const float sb_ = sqB[wn * 64 + nb * 8 + q * 2 + e0];
#pragma unroll
            for (int mb = 0; mb < 2; ++mb)
#pragma unroll
                for (int rr = 0; rr < 2; ++rr)
                    c[mb][nb][rr * 2 + e0] =
                        fmaf(c[mb][nb][rr * 2 + e0], 2.f, -sa0[mb * 2 + rr]) - sb_;
        }

    // ---- row MAX (pure FMNMX, no lists) ----
    float rm[4] = {NEG_INF, NEG_INF, NEG_INF, NEG_INF};
#pragma unroll
    for (int nb = 0; nb < 8; ++nb)
#pragma unroll
        for (int e0 = 0; e0 < 2; ++e0)
#pragma unroll
            for (int li = 0; li < 4; ++li)
                rm[li] = fmaxf(rm[li], c[li >> 1][nb][(li & 1) * 2 + e0]);
#pragma unroll
    for (int off = 1; off <= 2; off <<= 1)
#pragma unroll
        for (int li = 0; li < 4; ++li)
            rm[li] = fmaxf(rm[li], __shfl_xor_sync(0xffffffffu, rm[li], off));
    float* rowmaxs = (float*)(smem + SM_RM);
    if (q == 0) {
#pragma unroll
        for (int li = 0; li < 4; ++li) {
            const int rl = wm * 32 + (li >> 1) * 16 + (li & 1) * 8 + g;
            rowmaxs[wn * 128 + rl] = rm[li];
        }
    }
    __syncthreads();
    if (tid < 128)
        g_M[(size_t)(row0 + tid) * MS + J] = fmaxf(rowmaxs[tid], rowmaxs[128 + tid]);

    // ---- column MAX from T (off-diagonal tiles) ----
    if (J > I) {
        const int colX = tid & 127;
        const int half = tid >> 7;
        const float sbj = sqB[colX];
        float cm = NEG_INF;
        const float4* T4 = (const float4*)(T + colX * TSTRIDE + half * 64);
        const float4* A4 = (const float4*)(sqA + half * 64);
#pragma unroll
        for (int k = 0; k < 16; ++k) {
            const float4 f = T4[k];
            const float4 a = A4[k];
            cm = fmaxf(cm, (2.f * f.x - sbj) - a.x);
            cm = fmaxf(cm, (2.f * f.y - sbj) - a.y);
            cm = fmaxf(cm, (2.f * f.z - sbj) - a.z);
            cm = fmaxf(cm, (2.f * f.w - sbj) - a.w);
        }
        float* colmax = (float*)(smem + SM_CM);
        if (half) colmax[colX] = cm;
        __syncthreads();
        if (!half)
            g_M[(size_t)(col0 + colX) * MS + I] = fmaxf(cm, colmax[colX]);
    }
}

// ======================= phase 1.5: per-row tau + task building =======================
__global__ void select_kernel(int N) {
    const int wid  = threadIdx.x >> 5;
    const int lane = threadIdx.x & 31;
    const int row  = blockIdx.x * 8 + wid;
    if (row >= N) return;

    const float* Mr = g_M + (size_t)row * MS;
    float mv[KNN]; int mi[KNN];
#pragma unroll
    for (int m = 0; m < KNN; ++m) { mv[m] = NEG_INF; mi[m] = 0x7fffffff; }
    for (int s = lane; s < NB; s += 32) {
        const float v = Mr[s];
        if (knn_better(v, s, mv[0], mi[0])) topk_insert5(mv, mi, v, s);
    }
#pragma unroll
    for (int off = 16; off > 0; off >>= 1) {
        float ov[KNN]; int oi[KNN];
#pragma unroll
        for (int m = 0; m < KNN; ++m) {
            ov[m] = __shfl_down_sync(0xffffffffu, mv[m], off);
            oi[m] = __shfl_down_sync(0xffffffffu, mi[m], off);
        }
        if (lane < off) {
#pragma unroll
            for (int m = 0; m < KNN; ++m)
                if (oi[m] < NB && knn_better(ov[m], oi[m], mv[0], mi[0]))
                    topk_insert5(mv, mi, ov[m], oi[m]);
        }
    }
    const float tau = __shfl_sync(0xffffffffu, mv[0], 0);   // 5th-largest tile max
    if (lane == 0) g_tau[row] = tau;
    for (int s = lane; s < NB; s += 32) {
        if (Mr[s] >= tau) {
            const int slot = atomicAdd(&g_rowcnt[row], 1);
            if (slot < NSLOT2) {
                const int pos = atomicAdd(&g_blkcnt[s], 1);
                if (pos < MAXT) g_blkrows[(size_t)s * MAXT + pos] = (row << 4) | slot;
            }
        }
    }
}

// ======================= phase 2: fp32 dots, 4 tasks per warp pass, tau-filter ========
#define XS_STRIDE 76   // words per column: float4 phases hit 8 distinct bank groups
#define TBATCH 4
__global__ __launch_bounds__(256)
void refine_kernel(const float* __restrict__ x, int N) {
    __shared__ float xs[128 * XS_STRIDE];   // 38912 B
    __shared__ float sqs[128];

    const int b    = blockIdx.x;
    const int sub  = blockIdx.y;
    const int tid  = threadIdx.x;
    const int wid  = tid >> 5;
    const int lane = tid & 31;
    const int c0   = b * 128;

    for (int idx = tid; idx < 128 * D_FEAT; idx += 256) {
        const int j = idx >> 6, k = idx & 63;
        const int cg = c0 + j;
        xs[j * XS_STRIDE + k] = (cg < N) ? x[(size_t)cg * D_FEAT + k] : 0.f;
    }
    if (tid < 128) sqs[tid] = g_sq[c0 + tid];
    __syncthreads();

    const unsigned lmask = (1u << lane) - 1u;
    int cnt = g_blkcnt[b]; if (cnt > MAXT) cnt = MAXT;
    for (int t0 = (sub * 8 + wid) * TBATCH; t0 < cnt; t0 += 64 * TBATCH) {
        const int nt = (cnt - t0 < TBATCH) ? (cnt - t0) : TBATCH;   // warp-uniform
        int rowk[TBATCH], slotk[TBATCH];
        float sak[TBATCH];
        const float* xrk[TBATCH];
#pragma unroll
        for (int k = 0; k < TBATCH; ++k) {
            const int tt = (k < nt) ? (t0 + k) : t0;   // clamp: duplicate task 0 (not emitted)
            const int task = g_blkrows[(size_t)b * MAXT + tt];
            rowk[k]  = task >> 4;
            slotk[k] = task & 15;
            sak[k]   = g_sq[rowk[k]];
            xrk[k]   = x + (size_t)rowk[k] * D_FEAT;
        }

        // dot[k][cc]: 4 tasks x 4 columns per lane; ys loaded ONCE per f4 step
        float dot[TBATCH][4];
#pragma unroll
        for (int k = 0; k < TBATCH; ++k)
#pragma unroll
            for (int cc = 0; cc < 4; ++cc) dot[k][cc] = 0.f;

#pragma unroll
        for (int f4 = 0; f4 < 16; ++f4) {
            float4 ys[4];
#pragma unroll
            for (int cc = 0; cc < 4; ++cc)
                ys[cc] = *(const float4*)(xs + (lane + cc * 32) * XS_STRIDE + f4 * 4);
#pragma unroll
            for (int k = 0; k < TBATCH; ++k) {
                const float4 xv = __ldg((const float4*)(xrk[k] + f4 * 4));
#pragma unroll
                for (int cc = 0; cc < 4; ++cc) {
                    dot[k][cc] = fmaf(xv.x, ys[cc].x, dot[k][cc]);
                    dot[k][cc] = fmaf(xv.y, ys[cc].y, dot[k][cc]);
                    dot[k][cc] = fmaf(xv.z, ys[cc].z, dot[k][cc]);
                    dot[k][cc] = fmaf(xv.w, ys[cc].w, dot[k][cc]);
                }
            }
        }

        // filter + emit per task (nt is warp-uniform -> ballots stay converged)
        for (int k = 0; k < nt; ++k) {
            const float tauP = g_tau[rowk[k]] - TAU_MARGIN;
            float d[4]; bool pr[4]; unsigned bl[4]; int boff[4]; int tot = 0;
#pragma unroll
            for (int cc = 0; cc < 4; ++cc) {
                d[cc] = fmaf(dot[k][cc], 2.f, -sak[k]) - sqs[lane + cc * 32];
                pr[cc] = (d[cc] >= tauP);
                bl[cc] = __ballot_sync(0xffffffffu, pr[cc]);
                boff[cc] = tot;
                tot += __popc(bl[cc]);
            }
            const size_t sbase = ((size_t)rowk[k] * NSLOT2 + slotk[k]) * KNN;
            if (tot <= KNN) {
#pragma unroll
                for (int cc = 0; cc < 4; ++cc)
                    if (pr[cc]) {
                        const int pos = boff[cc] + __popc(bl[cc] & lmask);
                        g_topv[sbase + pos] = d[cc];
                        g_topi[sbase + pos] = c0 + lane + cc * 32;
                    }
            } else {
                // rare fallback: exact tile top-5 (tie-aware)
                float mv[KNN]; int mi[KNN];
#pragma unroll
                for (int m = 0; m < KNN; ++m) { mv[m] = NEG_INF; mi[m] = 0x7fffffff; }
#pragma unroll
                for (int cc = 0; cc < 4; ++cc)
                    topk_insert5(mv, mi, d[cc], c0 + lane + cc * 32);
#pragma unroll
                for (int off = 16; off > 0; off >>= 1) {
                    float ov[KNN]; int oi[KNN];
#pragma unroll
                    for (int m = 0; m < KNN; ++m) {
                        ov[m] = __shfl_down_sync(0xffffffffu, mv[m], off);
                        oi[m] = __shfl_down_sync(0xffffffffu, mi[m], off);
                    }
                    if (lane < off) {
#pragma unroll
                        for (int m = 0; m < KNN; ++m)
                            if (knn_better(ov[m], oi[m], mv[0], mi[0]))
                                topk_insert5(mv, mi, ov[m], oi[m]);
                    }
                }
                if (lane == 0) {
#pragma unroll
                    for (int m = 0; m < KNN; ++m) { g_topv[sbase + m] = mv[m]; g_topi[sbase + m] = mi[m]; }
                }
            }
        }
    }
}

// ======================= final merge (warp per row) + symmetric scatter ==============
__global__ void merge_scatter_kernel(float* __restrict__ out, int N) {
    const int wid  = threadIdx.x >> 5;
    const int lane = threadIdx.x & 31;
    const int row  = blockIdx.x * 8 + wid;
    if (row >= N) return;

    float mv[KNN]; int mi[KNN];
#pragma unroll
    for (int m = 0; m < KNN; ++m) { mv[m] = NEG_INF; mi[m] = 0x7fffffff; }

    const size_t base0 = (size_t)row * NSLOT2 * KNN;
    if (lane < NSLOT2) {
#pragma unroll
        for (int m = 0; m < KNN; ++m) {
            const float v = g_topv[base0 + lane * KNN + m];
            const int   j = g_topi[base0 + lane * KNN + m];
            if (j < N && knn_better(v, j, mv[0], mi[0])) topk_insert5(mv, mi, v, j);
        }
    }
#pragma unroll
    for (int off = 16; off > 0; off >>= 1) {
        float ov[KNN]; int oi[KNN];
#pragma unroll
        for (int m = 0; m < KNN; ++m) {
            ov[m] = __shfl_down_sync(0xffffffffu, mv[m], off);
            oi[m] = __shfl_down_sync(0xffffffffu, mi[m], off);
        }
        if (lane < off) {
#pragma unroll
            for (int m = 0; m < KNN; ++m)
                if (oi[m] < N && knn_better(ov[m], oi[m], mv[0], mi[0]))
                    topk_insert5(mv, mi, ov[m], oi[m]);
        }
    }
    // self (d~0) is the row max; reference zeroes the diagonal -> skip j == row.
    if (lane == 0) {
#pragma unroll
        for (int m = 0; m < KNN; ++m) {
            const int j = mi[m]; const float v = mv[m];
            if (j < N && j != row) {
                atomicAdd(out + (size_t)row * N + j, v);
                atomicAdd(out + (size_t)j * N + row, v);
            }
        }
    }
}

// ======================= launch =======================
extern "C" void kernel_launch(void* const* d_in, const int* in_sizes, int n_in,
                              void* d_out, int out_size) {
    const float* x = (const float*)d_in[0];
    const int N = in_sizes[0] / D_FEAT;   // 10000 here (<= NPADR)
    float* out = (float*)d_out;

    cudaFuncSetAttribute(gemm_max_kernel, cudaFuncAttributeMaxDynamicSharedMemorySize, SMEM_DYN);

    prep_kernel<<<(NPADR * 16 + 255) / 256, 256>>>(x, N);
    gemm_max_kernel<<<NPAIR, TPB, SMEM_DYN>>>(out, N);
    select_kernel<<<(N + 7) / 8, 256>>>(N);
    dim3 g2(NB, 8);
    refine_kernel<<<g2, 256>>>(x, N);
    merge_scatter_kernel<<<(N + 7) / 8, 256>>>(out, N);
}

// round 16
// speedup vs baseline: 2.6642x; 1.1599x over previous
#include <cuda_runtime.h>
#include <cuda_fp16.h>
#include <cstdint>

// ======================= constants =======================
#define D_FEAT  64
#define KNN     5
#define KH      64             // plain fp16 (hi only) — phase 1 is a filter now
#define TPB     256
#define NB      79             // number of 128-row blocks
#define NPAIR   (NB * (NB + 1) / 2)   // 3160 upper-triangular block pairs
#define NPADR   (NB * 128)     // 10112
#define MS      80             // row stride of the tile-max matrix M
#define NSLOT2  16             // phase-2 result slots per row
#define MAXT    4096           // max phase-2 tasks per column block
#define NEG_INF (-3.402823466e38f)
#define PAD_SQ  1.0e30f        // padded-row norm -> d ~ -1e30, never selected
#define TAU_MARGIN 0.25f       // > 2*eps(fp16 K=64 distance error ~0.02, 6sigma ~0.1)

// smem layout (bytes): row stride 144 (72 halfs) -> ldmatrix conflict-free (4r mod 32)
#define SAB      144
#define SM_A     0            // 128 x 144 = 18432
#define SM_B     18432        // 128 x 144 = 18432
// epilogue overlays (tile region reused as T after the MMA):
#define TSTRIDE  132          // words; 16B-aligned rows, conflict-free col scans
#define SM_T     0            // 128 cols x 132 x 4 = 67584
#define SM_RM    67584        // row maxes: 2 x 128 floats = 1024  (end 68608)
#define SM_CM    68608        // col maxes: 128 floats = 512       (end 69120)
// norms live BEYOND the T overlay (R15 bug: they were inside it and got clobbered)
#define SM_SQA   69120        // 128 floats (end 69632)
#define SM_SQB   69632        // 128 floats (end 70144)
#define SMEM_DYN 70144        // 3 CTAs/SM: 210 KB <= 228 KB

// ======================= device scratch (static; no allocs) =======================
__device__ __half g_xh[(size_t)NPADR * KH];   // fp16(x) — used as both A and B
__device__ float  g_sq[NPADR];
__device__ float  g_M[(size_t)NPADR * MS];    // per-(row, block) max distance (approx)
__device__ float  g_tau[NPADR];               // per-row 5th-largest tile max
__device__ int    g_rowcnt[NPADR];
__device__ int    g_blkcnt[NB];
__device__ int    g_blkrows[(size_t)NB * MAXT];   // (row << 4) | slot
__device__ float  g_topv[(size_t)NPADR * NSLOT2 * KNN];
__device__ int    g_topi[(size_t)NPADR * NSLOT2 * KNN];

// ======================= baseline-ISA PTX helpers (NO tcgen05) =======================
__device__ __forceinline__ uint32_t smem_to_u32(const void* p) {
    uint32_t a;
    asm("{ .reg .u64 t; cvta.to.shared.u64 t, %1; cvt.u32.u64 %0, t; }" : "=r"(a) : "l"(p));
    return a;
}
__device__ __forceinline__ void cp16(uint32_t dst, const void* src) {
    asm volatile("cp.async.cg.shared.global [%0], [%1], 16;" :: "r"(dst), "l"(src));
}
#define CP_COMMIT() asm volatile("cp.async.commit_group;" ::: "memory")
#define CP_WAIT(n)  asm volatile("cp.async.wait_group %0;" :: "n"(n) : "memory")

__device__ __forceinline__ void ldsm_x4(uint32_t* r, uint32_t addr) {
    asm volatile("ldmatrix.sync.aligned.m8n8.x4.shared.b16 {%0,%1,%2,%3}, [%4];"
                 : "=r"(r[0]), "=r"(r[1]), "=r"(r[2]), "=r"(r[3]) : "r"(addr));
}
__device__ __forceinline__ void mma16816(float* c, const uint32_t* a, const uint32_t* b) {
    asm volatile("mma.sync.aligned.m16n8k16.row.col.f32.f16.f16.f32 "
                 "{%0,%1,%2,%3}, {%4,%5,%6,%7}, {%8,%9}, {%0,%1,%2,%3};"
                 : "+f"(c[0]), "+f"(c[1]), "+f"(c[2]), "+f"(c[3])
                 : "r"(a[0]), "r"(a[1]), "r"(a[2]), "r"(a[3]), "r"(b[0]), "r"(b[1]));
}

// ======================= top-k =======================
__device__ __forceinline__ bool knn_better(float v, int i, float v2, int i2) {
    return (v > v2) || (v == v2 && i < i2);
}
__device__ __forceinline__ void topk_insert5(float* tv, int* ti, float v, int i) {
    bool cont = true;
#pragma unroll
    for (int s = 0; s < KNN; ++s) {
        bool up = (s < KNN - 1) && knn_better(v, i, tv[s + 1], ti[s + 1]);
        if (cont) {
            if (up) { tv[s] = tv[s + 1]; ti[s] = ti[s + 1]; }
            else    { tv[s] = v;          ti[s] = i; cont = false; }
        }
    }
}

// ======================= prep: fp16 convert + norms + counter/slot init ==============
__global__ void prep_kernel(const float* __restrict__ x, int N) {
    const int idx = blockIdx.x * blockDim.x + threadIdx.x;
    if (idx >= NPADR * 16) return;
    const int i  = idx >> 4;
    const int kq = idx & 15;
    const int k  = kq * 4;

    // init phase-2 slot indices (idx enumerates (row, slot) exactly) + counters
    {
        int* tb = g_topi + (size_t)idx * KNN;
#pragma unroll
        for (int m = 0; m < KNN; ++m) tb[m] = 0x7fffffff;
    }
    if (kq == 0) g_rowcnt[i] = 0;
    if (idx < NB) g_blkcnt[idx] = 0;

    float4 v4 = make_float4(0.f, 0.f, 0.f, 0.f);
    if (i < N) v4 = *(const float4*)(x + (size_t)i * D_FEAT + k);

    const float vv[4] = {v4.x, v4.y, v4.z, v4.w};
    __half h[4];
    float psum = 0.f;
#pragma unroll
    for (int e = 0; e < 4; ++e) {
        psum += vv[e] * vv[e];
        h[e] = __float2half_rn(vv[e]);
    }
    uint2 hp;
    hp.x = __half_as_ushort(h[0]) | ((uint32_t)__half_as_ushort(h[1]) << 16);
    hp.y = __half_as_ushort(h[2]) | ((uint32_t)__half_as_ushort(h[3]) << 16);
    *(uint2*)(g_xh + (size_t)i * KH + k) = hp;

#pragma unroll
    for (int s = 8; s > 0; s >>= 1) psum += __shfl_xor_sync(0xffffffffu, psum, s);
    if (kq == 0) g_sq[i] = (i < N) ? psum : PAD_SQ;
}

// ======================= phase 1: fp16 tile MMA -> per-(row, block) MAX ===============
__global__ __launch_bounds__(TPB, 3)
void gemm_max_kernel(float* __restrict__ out, int N) {
    extern __shared__ __align__(16) char smem[];
    const uint32_t sb = smem_to_u32(smem);
    float* sqA = (float*)(smem + SM_SQA);
    float* sqB = (float*)(smem + SM_SQB);

    const int tid  = threadIdx.x;
    const int w    = tid >> 5;
    const int lane = tid & 31;
    const int wm   = w & 3;
    const int wn   = w >> 2;
    const int g    = lane >> 2;
    const int q    = lane & 3;

    // blockIdx.x -> upper-triangular pair (I, J)
    const int pg = blockIdx.x;
    int I;
    {
        const float s0 = 2.f * NB + 1.f;
        I = (int)((s0 - sqrtf(s0 * s0 - 8.f * (float)pg)) * 0.5f);
        if (I < 0) I = 0; if (I > NB - 1) I = NB - 1;
        while (I > 0 && (I * NB - ((I * (I - 1)) >> 1)) > pg) --I;
        while (I < NB - 1 && ((I + 1) * NB - (((I + 1) * I) >> 1)) <= pg) ++I;
    }
    const int J = I + (pg - (I * NB - ((I * (I - 1)) >> 1)));
    const int row0 = I * 128;
    const int col0 = J * 128;

    const uint32_t aAddr0 = sb + SM_A + (uint32_t)(wm * 32 + (lane & 15)) * SAB + ((lane >> 4) * 8) * 2;
    const uint32_t aAddr1 = aAddr0 + 16 * SAB;
    uint32_t bAddr[4];
#pragma unroll
    for (int nb2 = 0; nb2 < 4; ++nb2)
        bAddr[nb2] = sb + SM_B + (uint32_t)(wn * 64 + nb2 * 16 + ((lane >> 4) << 3) + (lane & 7)) * SAB
                     + (((lane >> 3) & 1) * 8) * 2;

    // ---- async loads: 128 rows x 8 x 16B per tile ----
    for (int idx = tid; idx < 128 * 8; idx += TPB) {
        int r = idx >> 3, c = idx & 7;
        cp16(sb + SM_A + (uint32_t)r * SAB + c * 16,
             (const char*)(g_xh + (size_t)(row0 + r) * KH) + c * 16);
    }
    for (int idx = tid; idx < 128 * 8; idx += TPB) {
        int r = idx >> 3, c = idx & 7;
        cp16(sb + SM_B + (uint32_t)r * SAB + c * 16,
             (const char*)(g_xh + (size_t)(col0 + r) * KH) + c * 16);
    }
    if (tid < 128) sqA[tid] = g_sq[row0 + tid];
    else           sqB[tid - 128] = g_sq[col0 + tid - 128];
    CP_COMMIT();

    // zero this CTA's slice of the 400MB output while loads are in flight
    {
        const unsigned Z   = (unsigned)N * (unsigned)N;
        const unsigned per = (((Z + NPAIR - 1u) / NPAIR) + 3u) & ~3u;
        const unsigned lo  = (unsigned)pg * per;
        unsigned hi = lo + per; if (hi > Z) hi = Z;
        if (hi > lo) {
            float4* o4 = (float4*)(out + lo);
            const unsigned n4 = (hi - lo) >> 2;
            const float4 zz = make_float4(0.f, 0.f, 0.f, 0.f);
#pragma unroll 4
            for (unsigned i4 = tid; i4 < n4; i4 += TPB) __stcs(o4 + i4, zz);
            const unsigned tail = lo + (n4 << 2);
            if ((unsigned)tid < (hi - tail)) __stcs(out + tail + tid, 0.f);
        }
    }

    CP_WAIT(0);
    __syncthreads();

    // ---- 128x128x64 mainloop (4 k-steps) ----
    float c[2][8][4];
#pragma unroll
    for (int mb = 0; mb < 2; ++mb)
#pragma unroll
        for (int nb = 0; nb < 8; ++nb)
#pragma unroll
            for (int e = 0; e < 4; ++e) c[mb][nb][e] = 0.f;

#pragma unroll
    for (int ks = 0; ks < 4; ++ks) {
        uint32_t a0[4], a1[4], b[4][4];
        ldsm_x4(a0, aAddr0 + ks * 32);
        ldsm_x4(a1, aAddr1 + ks * 32);
#pragma unroll
        for (int nb2 = 0; nb2 < 4; ++nb2) ldsm_x4(b[nb2], bAddr[nb2] + ks * 32);
#pragma unroll
        for (int nb2 = 0; nb2 < 4; ++nb2) {
            mma16816(c[0][nb2 * 2],     a0, &b[nb2][0]);
            mma16816(c[0][nb2 * 2 + 1], a0, &b[nb2][2]);
            mma16816(c[1][nb2 * 2],     a1, &b[nb2][0]);
            mma16816(c[1][nb2 * 2 + 1], a1, &b[nb2][2]);
        }
    }

    __syncthreads();   // ldsm reads done -> tile region reusable as T

    // ---- store RAW dot to T for the column pass (T does NOT overlap sqA/sqB now) ----
    float* T = (float*)(smem + SM_T);
    if (J > I) {
#pragma unroll
        for (int mb = 0; mb < 2; ++mb)
#pragma unroll
            for (int nb = 0; nb < 8; ++nb)
#pragma unroll
                for (int rr = 0; rr < 2; ++rr)
#pragma unroll
                    for (int e0 = 0; e0 < 2; ++e0) {
                        const int cl = wn * 64 + nb * 8 + q * 2 + e0;
                        const int rl = wm * 32 + mb * 16 + rr * 8 + g;
                        T[cl * TSTRIDE + rl] = c[mb][nb][rr * 2 + e0];
                    }
    }

    // ---- transform c in place: d = (2*dot - sa) - sb ----
    float sa0[4];
#pragma unroll
    for (int mb = 0; mb < 2; ++mb)
#pragma unroll
        for (int rr = 0; rr < 2; ++rr)
            sa0[mb * 2 + rr] = sqA[wm * 32 + mb * 16 + rr * 8 + g];
#pragma unroll
    for (int nb = 0; nb < 8; ++nb)
#pragma unroll
        for (int e0 = 0; e0 < 2; ++e0) {
            const float sb_ = sqB[wn * 64 + nb * 8 + q * 2 + e0];
#pragma unroll
            for (int mb = 0; mb < 2; ++mb)
#pragma unroll
                for (int rr = 0; rr < 2; ++rr)
                    c[mb][nb][rr * 2 + e0] =
                        fmaf(c[mb][nb][rr * 2 + e0], 2.f, -sa0[mb * 2 + rr]) - sb_;
        }

    // ---- row MAX (pure FMNMX, no lists) ----
    float rm[4] = {NEG_INF, NEG_INF, NEG_INF, NEG_INF};
#pragma unroll
    for (int nb = 0; nb < 8; ++nb)
#pragma unroll
        for (int e0 = 0; e0 < 2; ++e0)
#pragma unroll
            for (int li = 0; li < 4; ++li)
                rm[li] = fmaxf(rm[li], c[li >> 1][nb][(li & 1) * 2 + e0]);
#pragma unroll
    for (int off = 1; off <= 2; off <<= 1)
#pragma unroll
        for (int li = 0; li < 4; ++li)
            rm[li] = fmaxf(rm[li], __shfl_xor_sync(0xffffffffu, rm[li], off));
    float* rowmaxs = (float*)(smem + SM_RM);
    if (q == 0) {
#pragma unroll
        for (int li = 0; li < 4; ++li) {
            const int rl = wm * 32 + (li >> 1) * 16 + (li & 1) * 8 + g;
            rowmaxs[wn * 128 + rl] = rm[li];
        }
    }
    __syncthreads();
    if (tid < 128)
        g_M[(size_t)(row0 + tid) * MS + J] = fmaxf(rowmaxs[tid], rowmaxs[128 + tid]);

    // ---- column MAX from T (off-diagonal tiles) ----
    if (J > I) {
        const int colX = tid & 127;
        const int half = tid >> 7;
        const float sbj = sqB[colX];
        float cm = NEG_INF;
        const float4* T4 = (const float4*)(T + colX * TSTRIDE + half * 64);
        const float4* A4 = (const float4*)(sqA + half * 64);
#pragma unroll
        for (int k = 0; k < 16; ++k) {
            const float4 f = T4[k];
            const float4 a = A4[k];
            cm = fmaxf(cm, (2.f * f.x - sbj) - a.x);
            cm = fmaxf(cm, (2.f * f.y - sbj) - a.y);
            cm = fmaxf(cm, (2.f * f.z - sbj) - a.z);
            cm = fmaxf(cm, (2.f * f.w - sbj) - a.w);
        }
        float* colmax = (float*)(smem + SM_CM);
        if (half) colmax[colX] = cm;
        __syncthreads();
        if (!half)
            g_M[(size_t)(col0 + colX) * MS + I] = fmaxf(cm, colmax[colX]);
    }
}

// ======================= phase 1.5: per-row tau + task building (with margin) ========
__global__ void select_kernel(int N) {
    const int wid  = threadIdx.x >> 5;
    const int lane = threadIdx.x & 31;
    const int row  = blockIdx.x * 8 + wid;
    if (row >= N) return;

    const float* Mr = g_M + (size_t)row * MS;
    float mv[KNN]; int mi[KNN];
#pragma unroll
    for (int m = 0; m < KNN; ++m) { mv[m] = NEG_INF; mi[m] = 0x7fffffff; }
    for (int s = lane; s < NB; s += 32) {
        const float v = Mr[s];
        if (knn_better(v, s, mv[0], mi[0])) topk_insert5(mv, mi, v, s);
    }
#pragma unroll
    for (int off = 16; off > 0; off >>= 1) {
        float ov[KNN]; int oi[KNN];
#pragma unroll
        for (int m = 0; m < KNN; ++m) {
            ov[m] = __shfl_down_sync(0xffffffffu, mv[m], off);
            oi[m] = __shfl_down_sync(0xffffffffu, mi[m], off);
        }
        if (lane < off) {
#pragma unroll
            for (int m = 0; m < KNN; ++m)
                if (oi[m] < NB && knn_better(ov[m], oi[m], mv[0], mi[0]))
                    topk_insert5(mv, mi, ov[m], oi[m]);
        }
    }
    const float tau = __shfl_sync(0xffffffffu, mv[0], 0);   // 5th-largest tile max
    if (lane == 0) g_tau[row] = tau;
    // margin on tile selection: covers fp16 phase-1 error (miss needs margin < 2*eps)
    const float thr = tau - TAU_MARGIN;
    for (int s = lane; s < NB; s += 32) {
        if (Mr[s] >= thr) {
            const int slot = atomicAdd(&g_rowcnt[row], 1);
            if (slot < NSLOT2) {
                const int pos = atomicAdd(&g_blkcnt[s], 1);
                if (pos < MAXT) g_blkrows[(size_t)s * MAXT + pos] = (row << 4) | slot;
            }
        }
    }
}

// ======================= phase 2: fp32 dots, 4 tasks per warp pass, tau-filter ========
#define XS_STRIDE 76   // words per column: float4 phases hit 8 distinct bank groups
#define TBATCH 4
__global__ __launch_bounds__(256)
void refine_kernel(const float* __restrict__ x, int N) {
    __shared__ float xs[128 * XS_STRIDE];   // 38912 B
    __shared__ float sqs[128];

    const int b    = blockIdx.x;
    const int sub  = blockIdx.y;
    const int tid  = threadIdx.x;
    const int wid  = tid >> 5;
    const int lane = tid & 31;
    const int c0   = b * 128;

    for (int idx = tid; idx < 128 * D_FEAT; idx += 256) {
        const int j = idx >> 6, k = idx & 63;
        const int cg = c0 + j;
        xs[j * XS_STRIDE + k] = (cg < N) ? x[(size_t)cg * D_FEAT + k] : 0.f;
    }
    if (tid < 128) sqs[tid] = g_sq[c0 + tid];
    __syncthreads();

    const unsigned lmask = (1u << lane) - 1u;
    int cnt = g_blkcnt[b]; if (cnt > MAXT) cnt = MAXT;
    for (int t0 = (sub * 8 + wid) * TBATCH; t0 < cnt; t0 += 64 * TBATCH) {
        const int nt = (cnt - t0 < TBATCH) ? (cnt - t0) : TBATCH;   // warp-uniform
        int rowk[TBATCH], slotk[TBATCH];
        float sak[TBATCH];
        const float* xrk[TBATCH];
#pragma unroll
        for (int k = 0; k < TBATCH; ++k) {
            const int tt = (k < nt) ? (t0 + k) : t0;   // clamp: duplicate task 0 (not emitted)
            const int task = g_blkrows[(size_t)b * MAXT + tt];
            rowk[k]  = task >> 4;
            slotk[k] = task & 15;
            sak[k]   = g_sq[rowk[k]];
            xrk[k]   = x + (size_t)rowk[k] * D_FEAT;
        }

        float dot[TBATCH][4];
#pragma unroll
        for (int k = 0; k < TBATCH; ++k)
#pragma unroll
            for (int cc = 0; cc < 4; ++cc) dot[k][cc] = 0.f;

#pragma unroll
        for (int f4 = 0; f4 < 16; ++f4) {
            float4 ys[4];
#pragma unroll
            for (int cc = 0; cc < 4; ++cc)
                ys[cc] = *(const float4*)(xs + (lane + cc * 32) * XS_STRIDE + f4 * 4);
#pragma unroll
            for (int k = 0; k < TBATCH; ++k) {
                const float4 xv = __ldg((const float4*)(xrk[k] + f4 * 4));
#pragma unroll
                for (int cc = 0; cc < 4; ++cc) {
                    dot[k][cc] = fmaf(xv.x, ys[cc].x, dot[k][cc]);
                    dot[k][cc] = fmaf(xv.y, ys[cc].y, dot[k][cc]);
                    dot[k][cc] = fmaf(xv.z, ys[cc].z, dot[k][cc]);
                    dot[k][cc] = fmaf(xv.w, ys[cc].w, dot[k][cc]);
                }
            }
        }

        for (int k = 0; k < nt; ++k) {
            const float tauP = g_tau[rowk[k]] - TAU_MARGIN;
            float d[4]; bool pr[4]; unsigned bl[4]; int boff[4]; int tot = 0;
#pragma unroll
            for (int cc = 0; cc < 4; ++cc) {
                d[cc] = fmaf(dot[k][cc], 2.f, -sak[k]) - sqs[lane + cc * 32];
                pr[cc] = (d[cc] >= tauP);
                bl[cc] = __ballot_sync(0xffffffffu, pr[cc]);
                boff[cc] = tot;
                tot += __popc(bl[cc]);
            }
            const size_t sbase = ((size_t)rowk[k] * NSLOT2 + slotk[k]) * KNN;
            if (tot <= KNN) {
#pragma unroll
                for (int cc = 0; cc < 4; ++cc)
                    if (pr[cc]) {
                        const int pos = boff[cc] + __popc(bl[cc] & lmask);
                        g_topv[sbase + pos] = d[cc];
                        g_topi[sbase + pos] = c0 + lane + cc * 32;
                    }
            } else {
                // fallback: exact tile top-5 (tie-aware)
                float mv[KNN]; int mi[KNN];
#pragma unroll
                for (int m = 0; m < KNN; ++m) { mv[m] = NEG_INF; mi[m] = 0x7fffffff; }
#pragma unroll
                for (int cc = 0; cc < 4; ++cc)
                    topk_insert5(mv, mi, d[cc], c0 + lane + cc * 32);
#pragma unroll
                for (int off = 16; off > 0; off >>= 1) {
                    float ov[KNN]; int oi[KNN];
#pragma unroll
                    for (int m = 0; m < KNN; ++m) {
                        ov[m] = __shfl_down_sync(0xffffffffu, mv[m], off);
                        oi[m] = __shfl_down_sync(0xffffffffu, mi[m], off);
                    }
                    if (lane < off) {
#pragma unroll
                        for (int m = 0; m < KNN; ++m)
                            if (knn_better(ov[m], oi[m], mv[0], mi[0]))
                                topk_insert5(mv, mi, ov[m], oi[m]);
                    }
                }
                if (lane == 0) {
#pragma unroll
                    for (int m = 0; m < KNN; ++m) { g_topv[sbase + m] = mv[m]; g_topi[sbase + m] = mi[m]; }
                }
            }
        }
    }
}

// ======================= final merge (warp per row) + symmetric scatter ==============
__global__ void merge_scatter_kernel(float* __restrict__ out, int N) {
    const int wid  = threadIdx.x >> 5;
    const int lane = threadIdx.x & 31;
    const int row  = blockIdx.x * 8 + wid;
    if (row >= N) return;

    float mv[KNN]; int mi[KNN];
#pragma unroll
    for (int m = 0; m < KNN; ++m) { mv[m] = NEG_INF; mi[m] = 0x7fffffff; }

    const size_t base0 = (size_t)row * NSLOT2 * KNN;
    if (lane < NSLOT2) {
#pragma unroll
        for (int m = 0; m < KNN; ++m) {
            const float v = g_topv[base0 + lane * KNN + m];
            const int   j = g_topi[base0 + lane * KNN + m];
            if (j < N && knn_better(v, j, mv[0], mi[0])) topk_insert5(mv, mi, v, j);
        }
    }
#pragma unroll
    for (int off = 16; off > 0; off >>= 1) {
        float ov[KNN]; int oi[KNN];
#pragma unroll
        for (int m = 0; m < KNN; ++m) {
            ov[m] = __shfl_down_sync(0xffffffffu, mv[m], off);
            oi[m] = __shfl_down_sync(0xffffffffu, mi[m], off);
        }
        if (lane < off) {
#pragma unroll
            for (int m = 0; m < KNN; ++m)
                if (oi[m] < N && knn_better(ov[m], oi[m], mv[0], mi[0]))
                    topk_insert5(mv, mi, ov[m], oi[m]);
        }
    }
    // self (d~0) is the row max; reference zeroes the diagonal -> skip j == row.
    if (lane == 0) {
#pragma unroll
        for (int m = 0; m < KNN; ++m) {
            const int j = mi[m]; const float v = mv[m];
            if (j < N && j != row) {
                atomicAdd(out + (size_t)row * N + j, v);
                atomicAdd(out + (size_t)j * N + row, v);
            }
        }
    }
}

// ======================= launch =======================
extern "C" void kernel_launch(void* const* d_in, const int* in_sizes, int n_in,
                              void* d_out, int out_size) {
    const float* x = (const float*)d_in[0];
    const int N = in_sizes[0] / D_FEAT;   // 10000 here (<= NPADR)
    float* out = (float*)d_out;

    cudaFuncSetAttribute(gemm_max_kernel, cudaFuncAttributeMaxDynamicSharedMemorySize, SMEM_DYN);

    prep_kernel<<<(NPADR * 16 + 255) / 256, 256>>>(x, N);
    gemm_max_kernel<<<NPAIR, TPB, SMEM_DYN>>>(out, N);
    select_kernel<<<(N + 7) / 8, 256>>>(N);
    dim3 g2(NB, 8);
    refine_kernel<<<g2, 256>>>(x, N);
    merge_scatter_kernel<<<(N + 7) / 8, 256>>>(out, N);
}

// round 17
// speedup vs baseline: 2.7364x; 1.0271x over previous
#include <cuda_runtime.h>
#include <cuda_fp16.h>
#include <cstdint>

// ======================= constants =======================
#define D_FEAT  64
#define KNN     5
#define KH      64             // plain fp16 (hi only) — phase 1 is a filter
#define TPB     256
#define NB      79             // number of 128-row blocks
#define NPAIR   (NB * (NB + 1) / 2)   // 3160 upper-triangular block pairs
#define NPADR   (NB * 128)     // 10112
#define MS      80             // row stride of the tile-max matrix M
#define NSLOT2  16             // phase-2 result slots per row
#define MAXT    4096           // max phase-2 tasks per column block
#define NREF    632            // refine CTAs (NB x 8)
#define NEG_INF (-3.402823466e38f)
#define PAD_SQ  1.0e30f        // padded-row norm -> d ~ -1e30, never selected
#define TAU_MARGIN 0.25f       // >> 2*eps(fp16 K=64 distance error, 6sigma ~0.1)

// smem layout (bytes): row stride 144 (72 halfs) -> ldmatrix conflict-free
#define SAB      144
#define SM_A     0            // 128 x 144 = 18432
#define SM_B     18432        // 128 x 144 = 18432  (end 36864)
#define SM_RM    36864        // row maxes: 2 x 128 floats = 1024   (end 37888)
#define SM_CW    37888        // col maxes: 4(wm) x 128 floats = 2048 (end 39936)
#define SM_SQA   39936        // 128 floats (end 40448)
#define SM_SQB   40448        // 128 floats (end 40960)
#define SMEM_DYN 40960        // no T overlay anymore — nothing overlaps

// ======================= device scratch (static; no allocs) =======================
__device__ __half g_xh[(size_t)NPADR * KH];   // fp16(x) — used as both A and B
__device__ float  g_sq[NPADR];
__device__ float  g_M[(size_t)NPADR * MS];    // per-(row, block) max distance (approx)
__device__ float  g_tau[NPADR];               // per-row 5th-largest tile max
__device__ int    g_rowcnt[NPADR];
__device__ int    g_blkcnt[NB];
__device__ int    g_blkrows[(size_t)NB * MAXT];   // (row << 4) | slot
__device__ float  g_topv[(size_t)NPADR * NSLOT2 * KNN];
__device__ int    g_topi[(size_t)NPADR * NSLOT2 * KNN];

// ======================= baseline-ISA PTX helpers (NO tcgen05) =======================
__device__ __forceinline__ uint32_t smem_to_u32(const void* p) {
    uint32_t a;
    asm("{ .reg .u64 t; cvta.to.shared.u64 t, %1; cvt.u32.u64 %0, t; }" : "=r"(a) : "l"(p));
    return a;
}
__device__ __forceinline__ void cp16(uint32_t dst, const void* src) {
    asm volatile("cp.async.cg.shared.global [%0], [%1], 16;" :: "r"(dst), "l"(src));
}
#define CP_COMMIT() asm volatile("cp.async.commit_group;" ::: "memory")
#define CP_WAIT(n)  asm volatile("cp.async.wait_group %0;" :: "n"(n) : "memory")

__device__ __forceinline__ void ldsm_x4(uint32_t* r, uint32_t addr) {
    asm volatile("ldmatrix.sync.aligned.m8n8.x4.shared.b16 {%0,%1,%2,%3}, [%4];"
                 : "=r"(r[0]), "=r"(r[1]), "=r"(r[2]), "=r"(r[3]) : "r"(addr));
}
__device__ __forceinline__ void mma16816(float* c, const uint32_t* a, const uint32_t* b) {
    asm volatile("mma.sync.aligned.m16n8k16.row.col.f32.f16.f16.f32 "
                 "{%0,%1,%2,%3}, {%4,%5,%6,%7}, {%8,%9}, {%0,%1,%2,%3};"
                 : "+f"(c[0]), "+f"(c[1]), "+f"(c[2]), "+f"(c[3])
                 : "r"(a[0]), "r"(a[1]), "r"(a[2]), "r"(a[3]), "r"(b[0]), "r"(b[1]));
}

// ======================= top-k =======================
__device__ __forceinline__ bool knn_better(float v, int i, float v2, int i2) {
    return (v > v2) || (v == v2 && i < i2);
}
__device__ __forceinline__ void topk_insert5(float* tv, int* ti, float v, int i) {
    bool cont = true;
#pragma unroll
    for (int s = 0; s < KNN; ++s) {
        bool up = (s < KNN - 1) && knn_better(v, i, tv[s + 1], ti[s + 1]);
        if (cont) {
            if (up) { tv[s] = tv[s + 1]; ti[s] = ti[s + 1]; }
            else    { tv[s] = v;          ti[s] = i; cont = false; }
        }
    }
}

// ======================= prep: fp16 convert + norms + counter/slot init ==============
__global__ void prep_kernel(const float* __restrict__ x, int N) {
    const int idx = blockIdx.x * blockDim.x + threadIdx.x;
    if (idx >= NPADR * 16) return;
    const int i  = idx >> 4;
    const int kq = idx & 15;
    const int k  = kq * 4;

    {
        int* tb = g_topi + (size_t)idx * KNN;
#pragma unroll
        for (int m = 0; m < KNN; ++m) tb[m] = 0x7fffffff;
    }
    if (kq == 0) g_rowcnt[i] = 0;
    if (idx < NB) g_blkcnt[idx] = 0;

    float4 v4 = make_float4(0.f, 0.f, 0.f, 0.f);
    if (i < N) v4 = *(const float4*)(x + (size_t)i * D_FEAT + k);

    const float vv[4] = {v4.x, v4.y, v4.z, v4.w};
    __half h[4];
    float psum = 0.f;
#pragma unroll
    for (int e = 0; e < 4; ++e) {
        psum += vv[e] * vv[e];
        h[e] = __float2half_rn(vv[e]);
    }
    uint2 hp;
    hp.x = __half_as_ushort(h[0]) | ((uint32_t)__half_as_ushort(h[1]) << 16);
    hp.y = __half_as_ushort(h[2]) | ((uint32_t)__half_as_ushort(h[3]) << 16);
    *(uint2*)(g_xh + (size_t)i * KH + k) = hp;

#pragma unroll
    for (int s = 8; s > 0; s >>= 1) psum += __shfl_xor_sync(0xffffffffu, psum, s);
    if (kq == 0) g_sq[i] = (i < N) ? psum : PAD_SQ;
}

// ======================= phase 1: fp16 tile MMA -> per-(row, block) MAX ===============
__global__ __launch_bounds__(TPB, 3)
void gemm_max_kernel(float* __restrict__ out, int N) {
    extern __shared__ __align__(16) char smem[];
    const uint32_t sb = smem_to_u32(smem);
    float* sqA = (float*)(smem + SM_SQA);
    float* sqB = (float*)(smem + SM_SQB);

    const int tid  = threadIdx.x;
    const int w    = tid >> 5;
    const int lane = tid & 31;
    const int wm   = w & 3;
    const int wn   = w >> 2;
    const int g    = lane >> 2;
    const int q    = lane & 3;

    // blockIdx.x -> upper-triangular pair (I, J)
    const int pg = blockIdx.x;
    int I;
    {
        const float s0 = 2.f * NB + 1.f;
        I = (int)((s0 - sqrtf(s0 * s0 - 8.f * (float)pg)) * 0.5f);
        if (I < 0) I = 0; if (I > NB - 1) I = NB - 1;
        while (I > 0 && (I * NB - ((I * (I - 1)) >> 1)) > pg) --I;
        while (I < NB - 1 && ((I + 1) * NB - (((I + 1) * I) >> 1)) <= pg) ++I;
    }
    const int J = I + (pg - (I * NB - ((I * (I - 1)) >> 1)));
    const int row0 = I * 128;
    const int col0 = J * 128;

    const uint32_t aAddr0 = sb + SM_A + (uint32_t)(wm * 32 + (lane & 15)) * SAB + ((lane >> 4) * 8) * 2;
    const uint32_t aAddr1 = aAddr0 + 16 * SAB;
    uint32_t bAddr[4];
#pragma unroll
    for (int nb2 = 0; nb2 < 4; ++nb2)
        bAddr[nb2] = sb + SM_B + (uint32_t)(wn * 64 + nb2 * 16 + ((lane >> 4) << 3) + (lane & 7)) * SAB
                     + (((lane >> 3) & 1) * 8) * 2;

    // ---- async loads: 128 rows x 8 x 16B per tile ----
    for (int idx = tid; idx < 128 * 8; idx += TPB) {
        int r = idx >> 3, c = idx & 7;
        cp16(sb + SM_A + (uint32_t)r * SAB + c * 16,
             (const char*)(g_xh + (size_t)(row0 + r) * KH) + c * 16);
    }
    for (int idx = tid; idx < 128 * 8; idx += TPB) {
        int r = idx >> 3, c = idx & 7;
        cp16(sb + SM_B + (uint32_t)r * SAB + c * 16,
             (const char*)(g_xh + (size_t)(col0 + r) * KH) + c * 16);
    }
    if (tid < 128) sqA[tid] = g_sq[row0 + tid];
    else           sqB[tid - 128] = g_sq[col0 + tid - 128];
    CP_COMMIT();

    // zero the FIRST HALF of the output (refine zeroes the rest), overlapped with loads
    {
        const unsigned Z   = (unsigned)N * (unsigned)N;
        const unsigned ZH  = ((Z >> 1) + 3u) & ~3u;          // first-half size, 16B aligned
        const unsigned per = (((ZH + NPAIR - 1u) / NPAIR) + 3u) & ~3u;
        const unsigned lo  = (unsigned)pg * per;
        unsigned hi = lo + per; if (hi > ZH) hi = ZH;
        if (hi > lo) {
            float4* o4 = (float4*)(out + lo);
            const unsigned n4 = (hi - lo) >> 2;
            const float4 zz = make_float4(0.f, 0.f, 0.f, 0.f);
#pragma unroll 4
            for (unsigned i4 = tid; i4 < n4; i4 += TPB) __stcs(o4 + i4, zz);
            const unsigned tail = lo + (n4 << 2);
            if ((unsigned)tid < (hi - tail)) __stcs(out + tail + tid, 0.f);
        }
    }

    CP_WAIT(0);
    __syncthreads();

    // ---- 128x128x64 mainloop (4 k-steps) ----
    float c[2][8][4];
#pragma unroll
    for (int mb = 0; mb < 2; ++mb)
#pragma unroll
        for (int nb = 0; nb < 8; ++nb)
#pragma unroll
            for (int e = 0; e < 4; ++e) c[mb][nb][e] = 0.f;

#pragma unroll
    for (int ks = 0; ks < 4; ++ks) {
        uint32_t a0[4], a1[4], b[4][4];
        ldsm_x4(a0, aAddr0 + ks * 32);
        ldsm_x4(a1, aAddr1 + ks * 32);
#pragma unroll
        for (int nb2 = 0; nb2 < 4; ++nb2) ldsm_x4(b[nb2], bAddr[nb2] + ks * 32);
#pragma unroll
        for (int nb2 = 0; nb2 < 4; ++nb2) {
            mma16816(c[0][nb2 * 2],     a0, &b[nb2][0]);
            mma16816(c[0][nb2 * 2 + 1], a0, &b[nb2][2]);
            mma16816(c[1][nb2 * 2],     a1, &b[nb2][0]);
            mma16816(c[1][nb2 * 2 + 1], a1, &b[nb2][2]);
        }
    }

    // ---- transform c in place: d = (2*dot - sa) - sb ----
    float sa0[4];
#pragma unroll
    for (int mb = 0; mb < 2; ++mb)
#pragma unroll
        for (int rr = 0; rr < 2; ++rr)
            sa0[mb * 2 + rr] = sqA[wm * 32 + mb * 16 + rr * 8 + g];
#pragma unroll
    for (int nb = 0; nb < 8; ++nb)
#pragma unroll
        for (int e0 = 0; e0 < 2; ++e0) {
            const float sb_ = sqB[wn * 64 + nb * 8 + q * 2 + e0];
#pragma unroll
            for (int mb = 0; mb < 2; ++mb)
#pragma unroll
                for (int rr = 0; rr < 2; ++rr)
                    c[mb][nb][rr * 2 + e0] =
                        fmaf(c[mb][nb][rr * 2 + e0], 2.f, -sa0[mb * 2 + rr]) - sb_;
        }

    // ---- row MAX (pure FMNMX + q-lane shuffles) ----
    float rm[4] = {NEG_INF, NEG_INF, NEG_INF, NEG_INF};
#pragma unroll
    for (int nb = 0; nb < 8; ++nb)
#pragma unroll
        for (int e0 = 0; e0 < 2; ++e0)
#pragma unroll
            for (int li = 0; li < 4; ++li)
                rm[li] = fmaxf(rm[li], c[li >> 1][nb][(li & 1) * 2 + e0]);
#pragma unroll
    for (int off = 1; off <= 2; off <<= 1)
#pragma unroll
        for (int li = 0; li < 4; ++li)
            rm[li] = fmaxf(rm[li], __shfl_xor_sync(0xffffffffu, rm[li], off));
    float* rowmaxs = (float*)(smem + SM_RM);
    if (q == 0) {
#pragma unroll
        for (int li = 0; li < 4; ++li) {
            const int rl = wm * 32 + (li >> 1) * 16 + (li & 1) * 8 + g;
            rowmaxs[wn * 128 + rl] = rm[li];
        }
    }

    // ---- column MAX straight from fragments (g-lane shuffles; no T transpose) ----
    // Uses row-rounding d values: <=1 ulp off the col-convention value, absorbed by margin.
    float* cw = (float*)(smem + SM_CW);   // [4(wm)][128]
    if (J > I) {
        float cmx[16];
#pragma unroll
        for (int nb = 0; nb < 8; ++nb)
#pragma unroll
            for (int e0 = 0; e0 < 2; ++e0)
                cmx[nb * 2 + e0] = fmaxf(fmaxf(c[0][nb][e0], c[0][nb][2 + e0]),
                                          fmaxf(c[1][nb][e0], c[1][nb][2 + e0]));
#pragma unroll
        for (int off = 4; off <= 16; off <<= 1)
#pragma unroll
            for (int t = 0; t < 16; ++t)
                cmx[t] = fmaxf(cmx[t], __shfl_xor_sync(0xffffffffu, cmx[t], off));
        if (g == 0) {
#pragma unroll
            for (int nb = 0; nb < 8; ++nb)
#pragma unroll
                for (int e0 = 0; e0 < 2; ++e0)
                    cw[wm * 128 + wn * 64 + nb * 8 + q * 2 + e0] = cmx[nb * 2 + e0];
        }
    }
    __syncthreads();

    if (tid < 128) {
        g_M[(size_t)(row0 + tid) * MS + J] = fmaxf(rowmaxs[tid], rowmaxs[128 + tid]);
        if (J > I) {
            const float m = fmaxf(fmaxf(cw[tid], cw[128 + tid]),
                                  fmaxf(cw[256 + tid], cw[384 + tid]));
            g_M[(size_t)(col0 + tid) * MS + I] = m;
        }
    }
}

// ======================= phase 1.5: per-row tau + task building (with margin) ========
__global__ void select_kernel(int N) {
    const int wid  = threadIdx.x >> 5;
    const int lane = threadIdx.x & 31;
    const int row  = blockIdx.x * 8 + wid;
    if (row >= N) return;

    const float* Mr = g_M + (size_t)row * MS;
    float mv[KNN]; int mi[KNN];
#pragma unroll
    for (int m = 0; m < KNN; ++m) { mv[m] = NEG_INF; mi[m] = 0x7fffffff; }
    for (int s = lane; s < NB; s += 32) {
        const float v = Mr[s];
        if (knn_better(v, s, mv[0], mi[0])) topk_insert5(mv, mi, v, s);
    }
#pragma unroll
    for (int off = 16; off > 0; off >>= 1) {
        float ov[KNN]; int oi[KNN];
#pragma unroll
        for (int m = 0; m < KNN; ++m) {
            ov[m] = __shfl_down_sync(0xffffffffu, mv[m], off);
            oi[m] = __shfl_down_sync(0xffffffffu, mi[m], off);
        }
        if (lane < off) {
#pragma unroll
            for (int m = 0; m < KNN; ++m)
                if (oi[m] < NB && knn_better(ov[m], oi[m], mv[0], mi[0]))
                    topk_insert5(mv, mi, ov[m], oi[m]);
        }
    }
    const float tau = __shfl_sync(0xffffffffu, mv[0], 0);   // 5th-largest tile max
    if (lane == 0) g_tau[row] = tau;
    const float thr = tau - TAU_MARGIN;
    for (int s = lane; s < NB; s += 32) {
        if (Mr[s] >= thr) {
            const int slot = atomicAdd(&g_rowcnt[row], 1);
            if (slot < NSLOT2) {
                const int pos = atomicAdd(&g_blkcnt[s], 1);
                if (pos < MAXT) g_blkrows[(size_t)s * MAXT + pos] = (row << 4) | slot;
            }
        }
    }
}

// ======================= phase 2: fp32 dots + tau-filter + 2nd-half zeroing ==========
#define XS_STRIDE 76   // words per column: float4 phases hit 8 distinct bank groups
#define TBATCH 4
__global__ __launch_bounds__(256)
void refine_kernel(const float* __restrict__ x, float* __restrict__ out, int N) {
    __shared__ float xs[128 * XS_STRIDE];   // 38912 B
    __shared__ float sqs[128];

    const int b    = blockIdx.x;
    const int sub  = blockIdx.y;
    const int tid  = threadIdx.x;
    const int wid  = tid >> 5;
    const int lane = tid & 31;
    const int c0   = b * 128;

    // zero the SECOND HALF of the output (drains under the compute below)
    {
        const unsigned Z   = (unsigned)N * (unsigned)N;
        const unsigned ZH  = ((Z >> 1) + 3u) & ~3u;
        const unsigned ZR  = Z - ZH;
        const unsigned cid = (unsigned)(sub * NB + b);
        const unsigned per = (((ZR + NREF - 1u) / NREF) + 3u) & ~3u;
        const unsigned lo  = ZH + cid * per;
        unsigned hi = lo + per; if (hi > Z) hi = Z;
        if (hi > lo) {
            float4* o4 = (float4*)(out + lo);
            const unsigned n4 = (hi - lo) >> 2;
            const float4 zz = make_float4(0.f, 0.f, 0.f, 0.f);
#pragma unroll 4
            for (unsigned i4 = tid; i4 < n4; i4 += 256) __stcs(o4 + i4, zz);
            const unsigned tail = lo + (n4 << 2);
            if ((unsigned)tid < (hi - tail)) __stcs(out + tail + tid, 0.f);
        }
    }

    for (int idx = tid; idx < 128 * D_FEAT; idx += 256) {
        const int j = idx >> 6, k = idx & 63;
        const int cg = c0 + j;
        xs[j * XS_STRIDE + k] = (cg < N) ? x[(size_t)cg * D_FEAT + k] : 0.f;
    }
    if (tid < 128) sqs[tid] = g_sq[c0 + tid];
    __syncthreads();

    const unsigned lmask = (1u << lane) - 1u;
    int cnt = g_blkcnt[b]; if (cnt > MAXT) cnt = MAXT;
    for (int t0 = (sub * 8 + wid) * TBATCH; t0 < cnt; t0 += 64 * TBATCH) {
        const int nt = (cnt - t0 < TBATCH) ? (cnt - t0) : TBATCH;   // warp-uniform
        int rowk[TBATCH], slotk[TBATCH];
        float sak[TBATCH];
        const float* xrk[TBATCH];
#pragma unroll
        for (int k = 0; k < TBATCH; ++k) {
            const int tt = (k < nt) ? (t0 + k) : t0;
            const int task = g_blkrows[(size_t)b * MAXT + tt];
            rowk[k]  = task >> 4;
            slotk[k] = task & 15;
            sak[k]   = g_sq[rowk[k]];
            xrk[k]   = x + (size_t)rowk[k] * D_FEAT;
        }

        float dot[TBATCH][4];
#pragma unroll
        for (int k = 0; k < TBATCH; ++k)
#pragma unroll
            for (int cc = 0; cc < 4; ++cc) dot[k][cc] = 0.f;

#pragma unroll
        for (int f4 = 0; f4 < 16; ++f4) {
            float4 ys[4];
#pragma unroll
            for (int cc = 0; cc < 4; ++cc)
                ys[cc] = *(const float4*)(xs + (lane + cc * 32) * XS_STRIDE + f4 * 4);
#pragma unroll
            for (int k = 0; k < TBATCH; ++k) {
                const float4 xv = __ldg((const float4*)(xrk[k] + f4 * 4));
#pragma unroll
                for (int cc = 0; cc < 4; ++cc) {
                    dot[k][cc] = fmaf(xv.x, ys[cc].x, dot[k][cc]);
                    dot[k][cc] = fmaf(xv.y, ys[cc].y, dot[k][cc]);
                    dot[k][cc] = fmaf(xv.z, ys[cc].z, dot[k][cc]);
                    dot[k][cc] = fmaf(xv.w, ys[cc].w, dot[k][cc]);
                }
            }
        }

        for (int k = 0; k < nt; ++k) {
            const float tauP = g_tau[rowk[k]] - TAU_MARGIN;
            float d[4]; bool pr[4]; unsigned bl[4]; int boff[4]; int tot = 0;
#pragma unroll
            for (int cc = 0; cc < 4; ++cc) {
                d[cc] = fmaf(dot[k][cc], 2.f, -sak[k]) - sqs[lane + cc * 32];
                pr[cc] = (d[cc] >= tauP);
                bl[cc] = __ballot_sync(0xffffffffu, pr[cc]);
                boff[cc] = tot;
                tot += __popc(bl[cc]);
            }
            const size_t sbase = ((size_t)rowk[k] * NSLOT2 + slotk[k]) * KNN;
            if (tot <= KNN) {
#pragma unroll
                for (int cc = 0; cc < 4; ++cc)
                    if (pr[cc]) {
                        const int pos = boff[cc] + __popc(bl[cc] & lmask);
                        g_topv[sbase + pos] = d[cc];
                        g_topi[sbase + pos] = c0 + lane + cc * 32;
                    }
            } else {
                float mv[KNN]; int mi[KNN];
#pragma unroll
                for (int m = 0; m < KNN; ++m) { mv[m] = NEG_INF; mi[m] = 0x7fffffff; }
#pragma unroll
                for (int cc = 0; cc < 4; ++cc)
                    topk_insert5(mv, mi, d[cc], c0 + lane + cc * 32);
#pragma unroll
                for (int off = 16; off > 0; off >>= 1) {
                    float ov[KNN]; int oi[KNN];
#pragma unroll
                    for (int m = 0; m < KNN; ++m) {
                        ov[m] = __shfl_down_sync(0xffffffffu, mv[m], off);
                        oi[m] = __shfl_down_sync(0xffffffffu, mi[m], off);
                    }
                    if (lane < off) {
#pragma unroll
                        for (int m = 0; m < KNN; ++m)
                            if (knn_better(ov[m], oi[m], mv[0], mi[0]))
                                topk_insert5(mv, mi, ov[m], oi[m]);
                    }
                }
                if (lane == 0) {
#pragma unroll
                    for (int m = 0; m < KNN; ++m) { g_topv[sbase + m] = mv[m]; g_topi[sbase + m] = mi[m]; }
                }
            }
        }
    }
}

// ======================= final merge (warp per row) + symmetric scatter ==============
__global__ void merge_scatter_kernel(float* __restrict__ out, int N) {
    const int wid  = threadIdx.x >> 5;
    const int lane = threadIdx.x & 31;
    const int row  = blockIdx.x * 8 + wid;
    if (row >= N) return;

    float mv[KNN]; int mi[KNN];
#pragma unroll
    for (int m = 0; m < KNN; ++m) { mv[m] = NEG_INF; mi[m] = 0x7fffffff; }

    const size_t base0 = (size_t)row * NSLOT2 * KNN;
    if (lane < NSLOT2) {
#pragma unroll
        for (int m = 0; m < KNN; ++m) {
            const float v = g_topv[base0 + lane * KNN + m];
            const int   j = g_topi[base0 + lane * KNN + m];
            if (j < N && knn_better(v, j, mv[0], mi[0])) topk_insert5(mv, mi, v, j);
        }
    }
#pragma unroll
    for (int off = 16; off > 0; off >>= 1) {
        float ov[KNN]; int oi[KNN];
#pragma unroll
        for (int m = 0; m < KNN; ++m) {
            ov[m] = __shfl_down_sync(0xffffffffu, mv[m], off);
            oi[m] = __shfl_down_sync(0xffffffffu, mi[m], off);
        }
        if (lane < off) {
#pragma unroll
            for (int m = 0; m < KNN; ++m)
                if (oi[m] < N && knn_better(ov[m], oi[m], mv[0], mi[0]))
                    topk_insert5(mv, mi, ov[m], oi[m]);
        }
    }
    // self (d~0) is the row max; reference zeroes the diagonal -> skip j == row.
    if (lane == 0) {
#pragma unroll
        for (int m = 0; m < KNN; ++m) {
            const int j = mi[m]; const float v = mv[m];
            if (j < N && j != row) {
                atomicAdd(out + (size_t)row * N + j, v);
                atomicAdd(out + (size_t)j * N + row, v);
            }
        }
    }
}

// ======================= launch =======================
extern "C" void kernel_launch(void* const* d_in, const int* in_sizes, int n_in,
                              void* d_out, int out_size) {
    const float* x = (const float*)d_in[0];
    const int N = in_sizes[0] / D_FEAT;   // 10000 here (<= NPADR)
    float* out = (float*)d_out;

    cudaFuncSetAttribute(gemm_max_kernel, cudaFuncAttributeMaxDynamicSharedMemorySize, SMEM_DYN);

    prep_kernel<<<(NPADR * 16 + 255) / 256, 256>>>(x, N);
    gemm_max_kernel<<<NPAIR, TPB, SMEM_DYN>>>(out, N);
    select_kernel<<<(N + 7) / 8, 256>>>(N);
    dim3 g2(NB, 8);
    refine_kernel<<<g2, 256>>>(x, out, N);
    merge_scatter_kernel<<<(N + 7) / 8, 256>>>(out, N);
}